// round 11
// baseline (speedup 1.0000x reference)
#include <cuda_runtime.h>

#define NS   50000
#define NT   50000
#define NN   100000
#define HN   50000
#define D    128
#define NEG  0.2f

#define BM   128
#define BK   16
#define SP   132          // padded smem row stride (floats); 132*4B = 16B-aligned
#define EMAX 1050000

// ---------------- scratch (device globals) ----------------------------------
__device__ float g_x[(size_t)NN * D];
__device__ float g_agg1[(size_t)HN * D];
__device__ float g_agg2[(size_t)HN * D];
__device__ float g_as1[NN], g_ad1[NN], g_as2[NN], g_ad2[NN];
__device__ float g_w1s[D], g_w1d[D], g_w2s[D], g_w2d[D];
__device__ int   g_cnt[HN];
__device__ int   g_ptr[HN + 1];
__device__ int   g_pos[HN];
__device__ int2  g_edge[EMAX];
__device__ int   g_is64;

__device__ __forceinline__ float lrelu(float v) { return v >= 0.f ? v : NEG * v; }

__device__ __forceinline__ void ffma2(unsigned long long& acc,
                                      unsigned long long a, unsigned long long b) {
    asm("fma.rn.f32x2 %0, %1, %2, %0;" : "+l"(acc) : "l"(a), "l"(b));
}
__device__ __forceinline__ unsigned long long dup2(float a) {
    unsigned long long r;
    asm("mov.b64 %0, {%1, %1};" : "=l"(r) : "r"(__float_as_uint(a)));
    return r;
}

// ---------------- index width detection -------------------------------------
__global__ void k_detect(const int* __restrict__ p) {
    if (threadIdx.x == 0) {
        int all0 = 1;
        #pragma unroll
        for (int i = 1; i < 128; i += 2) all0 &= (p[i] == 0);
        g_is64 = all0;
    }
}

__device__ __forceinline__ void load_edge(const void* idx, int off, int e,
                                          long long& v) {
    if (g_is64) v = ((const long long*)idx)[off + e];
    else        v = ((const int*)idx)[off + e];
}

// ---------------- wv = W^T @ a ----------------------------------------------
__global__ void k_wvec(const float* __restrict__ W1, const float* __restrict__ a1s,
                       const float* __restrict__ a1d,
                       const float* __restrict__ W2, const float* __restrict__ a2s,
                       const float* __restrict__ a2d) {
    int j = threadIdx.x;
    float s1 = 0.f, d1 = 0.f, s2 = 0.f, d2 = 0.f;
    for (int k = 0; k < D; k++) {
        float w1 = W1[k * D + j], w2 = W2[k * D + j];
        s1 = fmaf(w1, a1s[k], s1); d1 = fmaf(w1, a1d[k], d1);
        s2 = fmaf(w2, a2s[k], s2); d2 = fmaf(w2, a2d[k], d2);
    }
    g_w1s[j] = s1; g_w1d[j] = d1; g_w2s[j] = s2; g_w2d[j] = d2;
}

// ---------------- dual register-tiled SGEMM (f32x2, 8x16 thread tile) --------
// out[r,c] = act(bias[c] + in[r] . W[c,:]), two problems per grid.
// 128 threads; block tile 128x128; thread tile 8 rows x 16 cols.
// If do_att: also writes attention logits for nodes attBase+row.
__global__ __launch_bounds__(128, 2) void k_gemm2(
    const float* __restrict__ inA, const float* __restrict__ WA,
    const float* __restrict__ biasA, float* __restrict__ outA,
    const float* __restrict__ inB, const float* __restrict__ WB,
    const float* __restrict__ biasB, float* __restrict__ outB,
    int split, int rowsA, int rowsB, int relu, int do_att)
{
    __shared__ float As[BK][SP];
    __shared__ float Bs[BK][SP];

    const float *in, *W, *bias; float* out; int row0, nrows, attBase;
    if ((int)blockIdx.x < split) {
        in = inA; W = WA; bias = biasA; out = outA;
        row0 = blockIdx.x * BM; nrows = rowsA; attBase = 0;
    } else {
        in = inB; W = WB; bias = biasB; out = outB;
        row0 = (blockIdx.x - split) * BM; nrows = rowsB; attBase = NS;
    }

    const int tid = threadIdx.x;
    const int tr  = (tid >> 3) << 3;     // 16 row groups of 8
    const int tc  = (tid & 7) << 4;      // 8 col groups of 16

    unsigned long long acc[8][8];
    #pragma unroll
    for (int i = 0; i < 8; i++)
        #pragma unroll
        for (int j = 0; j < 8; j++) acc[i][j] = 0ull;

    for (int k0 = 0; k0 < D; k0 += BK) {
        __syncthreads();
        #pragma unroll
        for (int i = 0; i < 4; i++) {
            int lin = i * 128 + tid;          // 0..511
            int r   = lin >> 2;               // 0..127
            int jj  = (lin & 3) << 2;         // k offset 0,4,8,12
            int gr  = row0 + r;
            float4 v = make_float4(0.f, 0.f, 0.f, 0.f);
            if (gr < nrows) v = *(const float4*)(in + (size_t)gr * D + k0 + jj);
            As[jj + 0][r] = v.x; As[jj + 1][r] = v.y;
            As[jj + 2][r] = v.z; As[jj + 3][r] = v.w;
            float4 w = *(const float4*)(W + (size_t)r * D + k0 + jj);
            Bs[jj + 0][r] = w.x; Bs[jj + 1][r] = w.y;
            Bs[jj + 2][r] = w.z; Bs[jj + 3][r] = w.w;
        }
        __syncthreads();

        #pragma unroll
        for (int kk = 0; kk < BK; kk++) {
            float4 a0 = *(const float4*)&As[kk][tr];
            float4 a1 = *(const float4*)&As[kk][tr + 4];
            ulonglong2 w0 = *(const ulonglong2*)&Bs[kk][tc];
            ulonglong2 w1 = *(const ulonglong2*)&Bs[kk][tc + 4];
            ulonglong2 w2 = *(const ulonglong2*)&Bs[kk][tc + 8];
            ulonglong2 w3 = *(const ulonglong2*)&Bs[kk][tc + 12];
            float a[8] = {a0.x, a0.y, a0.z, a0.w, a1.x, a1.y, a1.z, a1.w};
            #pragma unroll
            for (int i = 0; i < 8; i++) {
                unsigned long long ap = dup2(a[i]);
                ffma2(acc[i][0], ap, w0.x);
                ffma2(acc[i][1], ap, w0.y);
                ffma2(acc[i][2], ap, w1.x);
                ffma2(acc[i][3], ap, w1.y);
                ffma2(acc[i][4], ap, w2.x);
                ffma2(acc[i][5], ap, w2.y);
                ffma2(acc[i][6], ap, w3.x);
                ffma2(acc[i][7], ap, w3.y);
            }
        }
    }

    float bcol[16];
    #pragma unroll
    for (int j = 0; j < 16; j++) bcol[j] = bias ? bias[tc + j] : 0.f;

    // attention vectors for this thread's 16 columns (only used when do_att)
    float v1s[16], v1d[16], v2s[16], v2d[16];
    if (do_att) {
        #pragma unroll
        for (int j = 0; j < 16; j++) {
            v1s[j] = g_w1s[tc + j]; v1d[j] = g_w1d[tc + j];
            v2s[j] = g_w2s[tc + j]; v2d[j] = g_w2d[tc + j];
        }
    }

    #pragma unroll
    for (int i = 0; i < 8; i++) {
        int gr = row0 + tr + i;
        float o[16];
        #pragma unroll
        for (int j = 0; j < 8; j++) {
            o[2 * j + 0] = __uint_as_float((unsigned)acc[i][j]) + bcol[2 * j + 0];
            o[2 * j + 1] = __uint_as_float((unsigned)(acc[i][j] >> 32)) + bcol[2 * j + 1];
        }
        if (relu) {
            #pragma unroll
            for (int j = 0; j < 16; j++) o[j] = fmaxf(o[j], 0.f);
        }
        if (gr < nrows) {
            *(float4*)(out + (size_t)gr * D + tc)      = make_float4(o[0], o[1], o[2], o[3]);
            *(float4*)(out + (size_t)gr * D + tc + 4)  = make_float4(o[4], o[5], o[6], o[7]);
            *(float4*)(out + (size_t)gr * D + tc + 8)  = make_float4(o[8], o[9], o[10], o[11]);
            *(float4*)(out + (size_t)gr * D + tc + 12) = make_float4(o[12], o[13], o[14], o[15]);
        }
        if (do_att) {
            float p1 = 0.f, p2 = 0.f, p3 = 0.f, p4 = 0.f;
            #pragma unroll
            for (int j = 0; j < 16; j++) {
                p1 = fmaf(o[j], v1s[j], p1);
                p2 = fmaf(o[j], v1d[j], p2);
                p3 = fmaf(o[j], v2s[j], p3);
                p4 = fmaf(o[j], v2d[j], p4);
            }
            #pragma unroll
            for (int m = 1; m < 8; m <<= 1) {
                p1 += __shfl_xor_sync(0xffffffffu, p1, m);
                p2 += __shfl_xor_sync(0xffffffffu, p2, m);
                p3 += __shfl_xor_sync(0xffffffffu, p3, m);
                p4 += __shfl_xor_sync(0xffffffffu, p4, m);
            }
            if ((tid & 7) == 0 && gr < nrows) {
                int node = attBase + gr;
                g_as1[node] = p1; g_ad1[node] = p2;
                g_as2[node] = p3; g_ad2[node] = p4;
            }
        }
    }
}

// ---------------- CSR pass 1: count edges per dst ----------------------------
__global__ void k_count(const void* __restrict__ idx, int dOff, int E,
                        int dAdd, int base) {
    int e = blockIdx.x * blockDim.x + threadIdx.x;
    if (e >= E) return;
    long long d; load_edge(idx, dOff, e, d);
    int di = (int)(d + dAdd) - base;
    if ((unsigned)di < (unsigned)HN) atomicAdd(&g_cnt[di], 1);
}

// ---------------- CSR pass 2: single-block exclusive scan --------------------
__global__ __launch_bounds__(1024) void k_scan() {
    __shared__ int wsum[32];
    int t = threadIdx.x, lane = t & 31, wid = t >> 5;
    int running = 0;
    for (int base = 0; base < HN; base += 1024) {
        int i = base + t;
        int v = (i < HN) ? g_cnt[i] : 0;
        int incl = v;
        #pragma unroll
        for (int o = 1; o < 32; o <<= 1) {
            int u = __shfl_up_sync(0xffffffffu, incl, o);
            if (lane >= o) incl += u;
        }
        if (lane == 31) wsum[wid] = incl;
        __syncthreads();
        if (wid == 0) {
            int s = wsum[lane];
            #pragma unroll
            for (int o = 1; o < 32; o <<= 1) {
                int u = __shfl_up_sync(0xffffffffu, s, o);
                if (lane >= o) s += u;
            }
            wsum[lane] = s;
        }
        __syncthreads();
        int woff = wid ? wsum[wid - 1] : 0;
        int excl = running + woff + incl - v;
        if (i < HN) { g_ptr[i] = excl; g_pos[i] = excl; }
        running += wsum[31];
        __syncthreads();
    }
    if (t == 0) g_ptr[HN] = running;
}

// ---------------- CSR pass 3: scatter (src, weight) --------------------------
__global__ void k_scatter(const void* __restrict__ idx, int sOff, int dOff, int E,
                          int sAdd, int dAdd, int base,
                          const float* __restrict__ as, const float* __restrict__ ad) {
    int e = blockIdx.x * blockDim.x + threadIdx.x;
    if (e >= E) return;
    long long s, d;
    load_edge(idx, sOff, e, s);
    load_edge(idx, dOff, e, d);
    int si = (int)(s + sAdd);
    int di = (int)(d + dAdd) - base;
    if ((unsigned)di >= (unsigned)HN) return;
    float w = __expf(lrelu(as[si] + ad[di + base]));
    int p = atomicAdd(&g_pos[di], 1);
    g_edge[p] = make_int2(si, __float_as_int(w));
}

// ---------------- aggregation: warp per dst, normalized output ---------------
__global__ void k_agg(int base, const float* __restrict__ as,
                      const float* __restrict__ ad, float* __restrict__ aggOut) {
    int i = (blockIdx.x * blockDim.x + threadIdx.x) >> 5;
    int lane = threadIdx.x & 31;
    if (i >= HN) return;
    int g = base + i;
    float w = __expf(lrelu(as[g] + ad[g]));        // self loop
    float denom = w;
    float4 xv = ((const float4*)g_x)[(size_t)g * 32 + lane];
    float4 acc = make_float4(xv.x * w, xv.y * w, xv.z * w, xv.w * w);
    int e0 = g_ptr[i], e1 = g_ptr[i + 1];
    for (int e = e0; e < e1; e++) {
        int2 ed = g_edge[e];
        float we = __int_as_float(ed.y);
        float4 xe = ((const float4*)g_x)[(size_t)ed.x * 32 + lane];
        acc.x = fmaf(xe.x, we, acc.x);
        acc.y = fmaf(xe.y, we, acc.y);
        acc.z = fmaf(xe.z, we, acc.z);
        acc.w = fmaf(xe.w, we, acc.w);
        denom += we;
    }
    float sc = 1.0f / (denom + 1e-16f);
    ((float4*)aggOut)[(size_t)i * 32 + lane] =
        make_float4(acc.x * sc, acc.y * sc, acc.z * sc, acc.w * sc);
}

// ---------------- driver ------------------------------------------------------
extern "C" void kernel_launch(void* const* d_in, const int* in_sizes, int n_in,
                              void* d_out, int out_size) {
    const void*  edge   = d_in[0];
    const void*  paper  = d_in[1];
    const void*  author = d_in[2];
    const float* x_s = (const float*)d_in[3];
    const float* x_t = (const float*)d_in[4];
    const float* Ws  = (const float*)d_in[5];
    const float* bs  = (const float*)d_in[6];
    const float* Wt  = (const float*)d_in[7];
    const float* bt  = (const float*)d_in[8];
    const float* W1  = (const float*)d_in[9];
    const float* a1s = (const float*)d_in[10];
    const float* a1d = (const float*)d_in[11];
    const float* W2  = (const float*)d_in[12];
    const float* a2s = (const float*)d_in[13];
    const float* a2d = (const float*)d_in[14];
    float* out = (float*)d_out;

    const int E0 = in_sizes[0] / 2;
    const int E1 = in_sizes[1] / 2;
    const int E2 = in_sizes[2] / 2;

    float* gx;    cudaGetSymbolAddress((void**)&gx,   g_x);
    float* gagg1; cudaGetSymbolAddress((void**)&gagg1, g_agg1);
    float* gagg2; cudaGetSymbolAddress((void**)&gagg2, g_agg2);
    float *gas1, *gad1, *gas2, *gad2;
    cudaGetSymbolAddress((void**)&gas1, g_as1);
    cudaGetSymbolAddress((void**)&gad1, g_ad1);
    cudaGetSymbolAddress((void**)&gas2, g_as2);
    cudaGetSymbolAddress((void**)&gad2, g_ad2);
    int* gcnt; cudaGetSymbolAddress((void**)&gcnt, g_cnt);

    const int GB = (NS + BM - 1) / BM;      // 391 blocks per 50K-row GEMM
    const int TB = 256;
    const int EB0 = (E0 + TB - 1) / TB;
    const int EB1 = (E1 + TB - 1) / TB;
    const int EB2 = (E2 + TB - 1) / TB;
    const int WNB = (HN * 32 + TB - 1) / TB;

    k_detect<<<1, 32>>>((const int*)edge);
    k_wvec<<<1, 128>>>(W1, a1s, a1d, W2, a2s, a2d);

    // fused input transforms + attention logits
    k_gemm2<<<2 * GB, 128>>>(x_s, Ws, bs, gx,
                             x_t, Wt, bt, gx + (size_t)NS * D,
                             GB, NS, NT, 0, 1);

    // ---- conv1: dst in [NS, NN) ----
    cudaMemsetAsync(gcnt, 0, HN * sizeof(int));
    k_count<<<EB0, TB>>>(edge,   E0, E0, NS, NS);
    k_count<<<EB2, TB>>>(author, E2, E2, 0,  NS);
    k_scan<<<1, 1024>>>();
    k_scatter<<<EB0, TB>>>(edge,   0, E0, E0, 0, NS, NS, gas1, gad1);
    k_scatter<<<EB2, TB>>>(author, 0, E2, E2, 0, 0,  NS, gas1, gad1);
    k_agg<<<WNB, TB>>>(NS, gas1, gad1, gagg1);

    // ---- conv2: dst in [0, NS) ----
    cudaMemsetAsync(gcnt, 0, HN * sizeof(int));
    k_count<<<EB0, TB>>>(edge,  0,  E0, 0, 0);
    k_count<<<EB1, TB>>>(paper, E1, E1, 0, 0);
    k_scan<<<1, 1024>>>();
    k_scatter<<<EB0, TB>>>(edge,  E0, 0,  E0, NS, 0, 0, gas2, gad2);
    k_scatter<<<EB1, TB>>>(paper, 0,  E1, E1, 0,  0, 0, gas2, gad2);
    k_agg<<<WNB, TB>>>(0, gas2, gad2, gagg2);

    // fused output GEMMs
    k_gemm2<<<2 * GB, 128>>>(gagg1, W1, nullptr, out + (size_t)NS * D,
                             gagg2, W2, nullptr, out,
                             GB, NS, NS, 1, 0);
}

// round 12
// speedup vs baseline: 1.0001x; 1.0001x over previous
#include <cuda_runtime.h>

#define NS   50000
#define NT   50000
#define NN   100000
#define HN   50000
#define D    128
#define NEG  0.2f

#define BM   128
#define BK   16
#define SP   132          // padded smem row stride (floats); 132*4B = 16B-aligned
#define EMAX 1050000

// ---------------- scratch (device globals) ----------------------------------
__device__ float g_x[(size_t)NN * D];
__device__ float g_agg1[(size_t)HN * D];
__device__ float g_agg2[(size_t)HN * D];
__device__ float g_as1[NN], g_ad1[NN], g_as2[NN], g_ad2[NN];
__device__ float g_w1s[D], g_w1d[D], g_w2s[D], g_w2d[D];
__device__ int   g_cnt[HN];
__device__ int   g_ptr[HN + 1];
__device__ int   g_pos[HN];
__device__ int2  g_edge[EMAX];
__device__ int   g_is64;

__device__ __forceinline__ float lrelu(float v) { return v >= 0.f ? v : NEG * v; }

__device__ __forceinline__ void ffma2(unsigned long long& acc,
                                      unsigned long long a, unsigned long long b) {
    asm("fma.rn.f32x2 %0, %1, %2, %0;" : "+l"(acc) : "l"(a), "l"(b));
}
__device__ __forceinline__ unsigned long long dup2(float a) {
    unsigned long long r;
    asm("mov.b64 %0, {%1, %1};" : "=l"(r) : "r"(__float_as_uint(a)));
    return r;
}

// ---------------- index width detection -------------------------------------
__global__ void k_detect(const int* __restrict__ p) {
    if (threadIdx.x == 0) {
        int all0 = 1;
        #pragma unroll
        for (int i = 1; i < 128; i += 2) all0 &= (p[i] == 0);
        g_is64 = all0;
    }
}

__device__ __forceinline__ void load_edge(const void* idx, int off, int e,
                                          long long& v) {
    if (g_is64) v = ((const long long*)idx)[off + e];
    else        v = ((const int*)idx)[off + e];
}

// ---------------- wv = W^T @ a ----------------------------------------------
__global__ void k_wvec(const float* __restrict__ W1, const float* __restrict__ a1s,
                       const float* __restrict__ a1d,
                       const float* __restrict__ W2, const float* __restrict__ a2s,
                       const float* __restrict__ a2d) {
    int j = threadIdx.x;
    float s1 = 0.f, d1 = 0.f, s2 = 0.f, d2 = 0.f;
    for (int k = 0; k < D; k++) {
        float w1 = W1[k * D + j], w2 = W2[k * D + j];
        s1 = fmaf(w1, a1s[k], s1); d1 = fmaf(w1, a1d[k], d1);
        s2 = fmaf(w2, a2s[k], s2); d2 = fmaf(w2, a2d[k], d2);
    }
    g_w1s[j] = s1; g_w1d[j] = d1; g_w2s[j] = s2; g_w2d[j] = d2;
}

// ---------------- dual register-tiled SGEMM (f32x2, 8x16 thread tile) --------
// out[r,c] = act(bias[c] + in[r] . W[c,:]), two problems per grid.
// 128 threads; block tile 128x128; thread tile 8 rows x 16 cols.
// If do_att: also writes attention logits for nodes attBase+row.
__global__ __launch_bounds__(128, 2) void k_gemm2(
    const float* __restrict__ inA, const float* __restrict__ WA,
    const float* __restrict__ biasA, float* __restrict__ outA,
    const float* __restrict__ inB, const float* __restrict__ WB,
    const float* __restrict__ biasB, float* __restrict__ outB,
    int split, int rowsA, int rowsB, int relu, int do_att)
{
    __shared__ float As[BK][SP];
    __shared__ float Bs[BK][SP];

    const float *in, *W, *bias; float* out; int row0, nrows, attBase;
    if ((int)blockIdx.x < split) {
        in = inA; W = WA; bias = biasA; out = outA;
        row0 = blockIdx.x * BM; nrows = rowsA; attBase = 0;
    } else {
        in = inB; W = WB; bias = biasB; out = outB;
        row0 = (blockIdx.x - split) * BM; nrows = rowsB; attBase = NS;
    }

    const int tid = threadIdx.x;
    const int tr  = (tid >> 3) << 3;     // 16 row groups of 8
    const int tc  = (tid & 7) << 4;      // 8 col groups of 16

    unsigned long long acc[8][8];
    #pragma unroll
    for (int i = 0; i < 8; i++)
        #pragma unroll
        for (int j = 0; j < 8; j++) acc[i][j] = 0ull;

    for (int k0 = 0; k0 < D; k0 += BK) {
        __syncthreads();
        #pragma unroll
        for (int i = 0; i < 4; i++) {
            int lin = i * 128 + tid;          // 0..511
            int r   = lin >> 2;               // 0..127
            int jj  = (lin & 3) << 2;         // k offset 0,4,8,12
            int gr  = row0 + r;
            float4 v = make_float4(0.f, 0.f, 0.f, 0.f);
            if (gr < nrows) v = *(const float4*)(in + (size_t)gr * D + k0 + jj);
            As[jj + 0][r] = v.x; As[jj + 1][r] = v.y;
            As[jj + 2][r] = v.z; As[jj + 3][r] = v.w;
            float4 w = *(const float4*)(W + (size_t)r * D + k0 + jj);
            Bs[jj + 0][r] = w.x; Bs[jj + 1][r] = w.y;
            Bs[jj + 2][r] = w.z; Bs[jj + 3][r] = w.w;
        }
        __syncthreads();

        #pragma unroll
        for (int kk = 0; kk < BK; kk++) {
            float4 a0 = *(const float4*)&As[kk][tr];
            float4 a1 = *(const float4*)&As[kk][tr + 4];
            ulonglong2 w0 = *(const ulonglong2*)&Bs[kk][tc];
            ulonglong2 w1 = *(const ulonglong2*)&Bs[kk][tc + 4];
            ulonglong2 w2 = *(const ulonglong2*)&Bs[kk][tc + 8];
            ulonglong2 w3 = *(const ulonglong2*)&Bs[kk][tc + 12];
            float a[8] = {a0.x, a0.y, a0.z, a0.w, a1.x, a1.y, a1.z, a1.w};
            #pragma unroll
            for (int i = 0; i < 8; i++) {
                unsigned long long ap = dup2(a[i]);
                ffma2(acc[i][0], ap, w0.x);
                ffma2(acc[i][1], ap, w0.y);
                ffma2(acc[i][2], ap, w1.x);
                ffma2(acc[i][3], ap, w1.y);
                ffma2(acc[i][4], ap, w2.x);
                ffma2(acc[i][5], ap, w2.y);
                ffma2(acc[i][6], ap, w3.x);
                ffma2(acc[i][7], ap, w3.y);
            }
        }
    }

    float bcol[16];
    #pragma unroll
    for (int j = 0; j < 16; j++) bcol[j] = bias ? bias[tc + j] : 0.f;

    // attention vectors for this thread's 16 columns (only used when do_att)
    float v1s[16], v1d[16], v2s[16], v2d[16];
    if (do_att) {
        #pragma unroll
        for (int j = 0; j < 16; j++) {
            v1s[j] = g_w1s[tc + j]; v1d[j] = g_w1d[tc + j];
            v2s[j] = g_w2s[tc + j]; v2d[j] = g_w2d[tc + j];
        }
    }

    #pragma unroll
    for (int i = 0; i < 8; i++) {
        int gr = row0 + tr + i;
        float o[16];
        #pragma unroll
        for (int j = 0; j < 8; j++) {
            o[2 * j + 0] = __uint_as_float((unsigned)acc[i][j]) + bcol[2 * j + 0];
            o[2 * j + 1] = __uint_as_float((unsigned)(acc[i][j] >> 32)) + bcol[2 * j + 1];
        }
        if (relu) {
            #pragma unroll
            for (int j = 0; j < 16; j++) o[j] = fmaxf(o[j], 0.f);
        }
        if (gr < nrows) {
            *(float4*)(out + (size_t)gr * D + tc)      = make_float4(o[0], o[1], o[2], o[3]);
            *(float4*)(out + (size_t)gr * D + tc + 4)  = make_float4(o[4], o[5], o[6], o[7]);
            *(float4*)(out + (size_t)gr * D + tc + 8)  = make_float4(o[8], o[9], o[10], o[11]);
            *(float4*)(out + (size_t)gr * D + tc + 12) = make_float4(o[12], o[13], o[14], o[15]);
        }
        if (do_att) {
            float p1 = 0.f, p2 = 0.f, p3 = 0.f, p4 = 0.f;
            #pragma unroll
            for (int j = 0; j < 16; j++) {
                p1 = fmaf(o[j], v1s[j], p1);
                p2 = fmaf(o[j], v1d[j], p2);
                p3 = fmaf(o[j], v2s[j], p3);
                p4 = fmaf(o[j], v2d[j], p4);
            }
            #pragma unroll
            for (int m = 1; m < 8; m <<= 1) {
                p1 += __shfl_xor_sync(0xffffffffu, p1, m);
                p2 += __shfl_xor_sync(0xffffffffu, p2, m);
                p3 += __shfl_xor_sync(0xffffffffu, p3, m);
                p4 += __shfl_xor_sync(0xffffffffu, p4, m);
            }
            if ((tid & 7) == 0 && gr < nrows) {
                int node = attBase + gr;
                g_as1[node] = p1; g_ad1[node] = p2;
                g_as2[node] = p3; g_ad2[node] = p4;
            }
        }
    }
}

// ---------------- CSR pass 1: count edges per dst ----------------------------
__global__ void k_count(const void* __restrict__ idx, int dOff, int E,
                        int dAdd, int base) {
    int e = blockIdx.x * blockDim.x + threadIdx.x;
    if (e >= E) return;
    long long d; load_edge(idx, dOff, e, d);
    int di = (int)(d + dAdd) - base;
    if ((unsigned)di < (unsigned)HN) atomicAdd(&g_cnt[di], 1);
}

// ---------------- CSR pass 2: single-block exclusive scan --------------------
__global__ __launch_bounds__(1024) void k_scan() {
    __shared__ int wsum[32];
    int t = threadIdx.x, lane = t & 31, wid = t >> 5;
    int running = 0;
    for (int base = 0; base < HN; base += 1024) {
        int i = base + t;
        int v = (i < HN) ? g_cnt[i] : 0;
        int incl = v;
        #pragma unroll
        for (int o = 1; o < 32; o <<= 1) {
            int u = __shfl_up_sync(0xffffffffu, incl, o);
            if (lane >= o) incl += u;
        }
        if (lane == 31) wsum[wid] = incl;
        __syncthreads();
        if (wid == 0) {
            int s = wsum[lane];
            #pragma unroll
            for (int o = 1; o < 32; o <<= 1) {
                int u = __shfl_up_sync(0xffffffffu, s, o);
                if (lane >= o) s += u;
            }
            wsum[lane] = s;
        }
        __syncthreads();
        int woff = wid ? wsum[wid - 1] : 0;
        int excl = running + woff + incl - v;
        if (i < HN) { g_ptr[i] = excl; g_pos[i] = excl; }
        running += wsum[31];
        __syncthreads();
    }
    if (t == 0) g_ptr[HN] = running;
}

// ---------------- CSR pass 3: scatter (src, weight) --------------------------
__global__ void k_scatter(const void* __restrict__ idx, int sOff, int dOff, int E,
                          int sAdd, int dAdd, int base,
                          const float* __restrict__ as, const float* __restrict__ ad) {
    int e = blockIdx.x * blockDim.x + threadIdx.x;
    if (e >= E) return;
    long long s, d;
    load_edge(idx, sOff, e, s);
    load_edge(idx, dOff, e, d);
    int si = (int)(s + sAdd);
    int di = (int)(d + dAdd) - base;
    if ((unsigned)di >= (unsigned)HN) return;
    float w = __expf(lrelu(as[si] + ad[di + base]));
    int p = atomicAdd(&g_pos[di], 1);
    g_edge[p] = make_int2(si, __float_as_int(w));
}

// ---------------- aggregation: warp per dst, normalized output ---------------
__global__ void k_agg(int base, const float* __restrict__ as,
                      const float* __restrict__ ad, float* __restrict__ aggOut) {
    int i = (blockIdx.x * blockDim.x + threadIdx.x) >> 5;
    int lane = threadIdx.x & 31;
    if (i >= HN) return;
    int g = base + i;
    float w = __expf(lrelu(as[g] + ad[g]));        // self loop
    float denom = w;
    float4 xv = ((const float4*)g_x)[(size_t)g * 32 + lane];
    float4 acc = make_float4(xv.x * w, xv.y * w, xv.z * w, xv.w * w);
    int e0 = g_ptr[i], e1 = g_ptr[i + 1];
    for (int e = e0; e < e1; e++) {
        int2 ed = g_edge[e];
        float we = __int_as_float(ed.y);
        float4 xe = ((const float4*)g_x)[(size_t)ed.x * 32 + lane];
        acc.x = fmaf(xe.x, we, acc.x);
        acc.y = fmaf(xe.y, we, acc.y);
        acc.z = fmaf(xe.z, we, acc.z);
        acc.w = fmaf(xe.w, we, acc.w);
        denom += we;
    }
    float sc = 1.0f / (denom + 1e-16f);
    ((float4*)aggOut)[(size_t)i * 32 + lane] =
        make_float4(acc.x * sc, acc.y * sc, acc.z * sc, acc.w * sc);
}

// ---------------- driver ------------------------------------------------------
extern "C" void kernel_launch(void* const* d_in, const int* in_sizes, int n_in,
                              void* d_out, int out_size) {
    const void*  edge   = d_in[0];
    const void*  paper  = d_in[1];
    const void*  author = d_in[2];
    const float* x_s = (const float*)d_in[3];
    const float* x_t = (const float*)d_in[4];
    const float* Ws  = (const float*)d_in[5];
    const float* bs  = (const float*)d_in[6];
    const float* Wt  = (const float*)d_in[7];
    const float* bt  = (const float*)d_in[8];
    const float* W1  = (const float*)d_in[9];
    const float* a1s = (const float*)d_in[10];
    const float* a1d = (const float*)d_in[11];
    const float* W2  = (const float*)d_in[12];
    const float* a2s = (const float*)d_in[13];
    const float* a2d = (const float*)d_in[14];
    float* out = (float*)d_out;

    const int E0 = in_sizes[0] / 2;
    const int E1 = in_sizes[1] / 2;
    const int E2 = in_sizes[2] / 2;

    float* gx;    cudaGetSymbolAddress((void**)&gx,   g_x);
    float* gagg1; cudaGetSymbolAddress((void**)&gagg1, g_agg1);
    float* gagg2; cudaGetSymbolAddress((void**)&gagg2, g_agg2);
    float *gas1, *gad1, *gas2, *gad2;
    cudaGetSymbolAddress((void**)&gas1, g_as1);
    cudaGetSymbolAddress((void**)&gad1, g_ad1);
    cudaGetSymbolAddress((void**)&gas2, g_as2);
    cudaGetSymbolAddress((void**)&gad2, g_ad2);
    int* gcnt; cudaGetSymbolAddress((void**)&gcnt, g_cnt);

    const int GB = (NS + BM - 1) / BM;      // 391 blocks per 50K-row GEMM
    const int TB = 256;
    const int EB0 = (E0 + TB - 1) / TB;
    const int EB1 = (E1 + TB - 1) / TB;
    const int EB2 = (E2 + TB - 1) / TB;
    const int WNB = (HN * 32 + TB - 1) / TB;

    k_detect<<<1, 32>>>((const int*)edge);
    k_wvec<<<1, 128>>>(W1, a1s, a1d, W2, a2s, a2d);

    // fused input transforms + attention logits
    k_gemm2<<<2 * GB, 128>>>(x_s, Ws, bs, gx,
                             x_t, Wt, bt, gx + (size_t)NS * D,
                             GB, NS, NT, 0, 1);

    // ---- conv1: dst in [NS, NN) ----
    cudaMemsetAsync(gcnt, 0, HN * sizeof(int));
    k_count<<<EB0, TB>>>(edge,   E0, E0, NS, NS);
    k_count<<<EB2, TB>>>(author, E2, E2, 0,  NS);
    k_scan<<<1, 1024>>>();
    k_scatter<<<EB0, TB>>>(edge,   0, E0, E0, 0, NS, NS, gas1, gad1);
    k_scatter<<<EB2, TB>>>(author, 0, E2, E2, 0, 0,  NS, gas1, gad1);
    k_agg<<<WNB, TB>>>(NS, gas1, gad1, gagg1);

    // ---- conv2: dst in [0, NS) ----
    cudaMemsetAsync(gcnt, 0, HN * sizeof(int));
    k_count<<<EB0, TB>>>(edge,  0,  E0, 0, 0);
    k_count<<<EB1, TB>>>(paper, E1, E1, 0, 0);
    k_scan<<<1, 1024>>>();
    k_scatter<<<EB0, TB>>>(edge,  E0, 0,  E0, NS, 0, 0, gas2, gad2);
    k_scatter<<<EB1, TB>>>(paper, 0,  E1, E1, 0,  0, 0, gas2, gad2);
    k_agg<<<WNB, TB>>>(0, gas2, gad2, gagg2);

    // fused output GEMMs
    k_gemm2<<<2 * GB, 128>>>(gagg1, W1, nullptr, out + (size_t)NS * D,
                             gagg2, W2, nullptr, out,
                             GB, NS, NS, 1, 0);
}

// round 13
// speedup vs baseline: 1.0008x; 1.0007x over previous
#include <cuda_runtime.h>

#define NS   50000
#define NT   50000
#define NN   100000
#define HN   50000
#define D    128
#define NEG  0.2f

#define BM   128
#define BK   16
#define SP   132          // padded smem row stride (floats); 132*4B = 16B-aligned
#define EMAX 1050000

// ---------------- scratch (device globals) ----------------------------------
__device__ float g_x[(size_t)NN * D];
__device__ float g_agg1[(size_t)HN * D];
__device__ float g_agg2[(size_t)HN * D];
__device__ float g_as1[NN], g_ad1[NN], g_as2[NN], g_ad2[NN];
__device__ float g_w1s[D], g_w1d[D], g_w2s[D], g_w2d[D];
__device__ int   g_cnt[HN];
__device__ int   g_ptr[HN + 1];
__device__ int   g_pos[HN];
__device__ int2  g_edge[EMAX];
__device__ int   g_is64;

__device__ __forceinline__ float lrelu(float v) { return v >= 0.f ? v : NEG * v; }

__device__ __forceinline__ void ffma2(unsigned long long& acc,
                                      unsigned long long a, unsigned long long b) {
    asm("fma.rn.f32x2 %0, %1, %2, %0;" : "+l"(acc) : "l"(a), "l"(b));
}
__device__ __forceinline__ unsigned long long dup2(float a) {
    unsigned long long r;
    asm("mov.b64 %0, {%1, %1};" : "=l"(r) : "r"(__float_as_uint(a)));
    return r;
}

// ---------------- index width detection -------------------------------------
__global__ void k_detect(const int* __restrict__ p) {
    if (threadIdx.x == 0) {
        int all0 = 1;
        #pragma unroll
        for (int i = 1; i < 128; i += 2) all0 &= (p[i] == 0);
        g_is64 = all0;
    }
}

__device__ __forceinline__ void load_edge(const void* idx, int off, int e,
                                          long long& v) {
    if (g_is64) v = ((const long long*)idx)[off + e];
    else        v = ((const int*)idx)[off + e];
}

// ---------------- wv = W^T @ a ----------------------------------------------
__global__ void k_wvec(const float* __restrict__ W1, const float* __restrict__ a1s,
                       const float* __restrict__ a1d,
                       const float* __restrict__ W2, const float* __restrict__ a2s,
                       const float* __restrict__ a2d) {
    int j = threadIdx.x;
    float s1 = 0.f, d1 = 0.f, s2 = 0.f, d2 = 0.f;
    for (int k = 0; k < D; k++) {
        float w1 = W1[k * D + j], w2 = W2[k * D + j];
        s1 = fmaf(w1, a1s[k], s1); d1 = fmaf(w1, a1d[k], d1);
        s2 = fmaf(w2, a2s[k], s2); d2 = fmaf(w2, a2d[k], d2);
    }
    g_w1s[j] = s1; g_w1d[j] = d1; g_w2s[j] = s2; g_w2d[j] = d2;
}

// ---------------- dual register-tiled SGEMM (f32x2, 8x16 thread tile) --------
// out[r,c] = act(bias[c] + in[r] . W[c,:]), two problems per grid.
// 128 threads; block tile 128x128; thread tile 8 rows x 16 cols.
// If do_att: also writes attention logits for nodes attBase+row.
__global__ __launch_bounds__(128, 2) void k_gemm2(
    const float* __restrict__ inA, const float* __restrict__ WA,
    const float* __restrict__ biasA, float* __restrict__ outA,
    const float* __restrict__ inB, const float* __restrict__ WB,
    const float* __restrict__ biasB, float* __restrict__ outB,
    int split, int rowsA, int rowsB, int relu, int do_att)
{
    __shared__ float As[BK][SP];
    __shared__ float Bs[BK][SP];

    const float *in, *W, *bias; float* out; int row0, nrows, attBase;
    if ((int)blockIdx.x < split) {
        in = inA; W = WA; bias = biasA; out = outA;
        row0 = blockIdx.x * BM; nrows = rowsA; attBase = 0;
    } else {
        in = inB; W = WB; bias = biasB; out = outB;
        row0 = (blockIdx.x - split) * BM; nrows = rowsB; attBase = NS;
    }

    const int tid = threadIdx.x;
    const int tr  = (tid >> 3) << 3;     // 16 row groups of 8
    const int tc  = (tid & 7) << 4;      // 8 col groups of 16

    unsigned long long acc[8][8];
    #pragma unroll
    for (int i = 0; i < 8; i++)
        #pragma unroll
        for (int j = 0; j < 8; j++) acc[i][j] = 0ull;

    for (int k0 = 0; k0 < D; k0 += BK) {
        __syncthreads();
        #pragma unroll
        for (int i = 0; i < 4; i++) {
            int lin = i * 128 + tid;          // 0..511
            int r   = lin >> 2;               // 0..127
            int jj  = (lin & 3) << 2;         // k offset 0,4,8,12
            int gr  = row0 + r;
            float4 v = make_float4(0.f, 0.f, 0.f, 0.f);
            if (gr < nrows) v = *(const float4*)(in + (size_t)gr * D + k0 + jj);
            As[jj + 0][r] = v.x; As[jj + 1][r] = v.y;
            As[jj + 2][r] = v.z; As[jj + 3][r] = v.w;
            float4 w = *(const float4*)(W + (size_t)r * D + k0 + jj);
            Bs[jj + 0][r] = w.x; Bs[jj + 1][r] = w.y;
            Bs[jj + 2][r] = w.z; Bs[jj + 3][r] = w.w;
        }
        __syncthreads();

        #pragma unroll
        for (int kk = 0; kk < BK; kk++) {
            float4 a0 = *(const float4*)&As[kk][tr];
            float4 a1 = *(const float4*)&As[kk][tr + 4];
            ulonglong2 w0 = *(const ulonglong2*)&Bs[kk][tc];
            ulonglong2 w1 = *(const ulonglong2*)&Bs[kk][tc + 4];
            ulonglong2 w2 = *(const ulonglong2*)&Bs[kk][tc + 8];
            ulonglong2 w3 = *(const ulonglong2*)&Bs[kk][tc + 12];
            float a[8] = {a0.x, a0.y, a0.z, a0.w, a1.x, a1.y, a1.z, a1.w};
            #pragma unroll
            for (int i = 0; i < 8; i++) {
                unsigned long long ap = dup2(a[i]);
                ffma2(acc[i][0], ap, w0.x);
                ffma2(acc[i][1], ap, w0.y);
                ffma2(acc[i][2], ap, w1.x);
                ffma2(acc[i][3], ap, w1.y);
                ffma2(acc[i][4], ap, w2.x);
                ffma2(acc[i][5], ap, w2.y);
                ffma2(acc[i][6], ap, w3.x);
                ffma2(acc[i][7], ap, w3.y);
            }
        }
    }

    float bcol[16];
    #pragma unroll
    for (int j = 0; j < 16; j++) bcol[j] = bias ? bias[tc + j] : 0.f;

    // attention vectors for this thread's 16 columns (only used when do_att)
    float v1s[16], v1d[16], v2s[16], v2d[16];
    if (do_att) {
        #pragma unroll
        for (int j = 0; j < 16; j++) {
            v1s[j] = g_w1s[tc + j]; v1d[j] = g_w1d[tc + j];
            v2s[j] = g_w2s[tc + j]; v2d[j] = g_w2d[tc + j];
        }
    }

    #pragma unroll
    for (int i = 0; i < 8; i++) {
        int gr = row0 + tr + i;
        float o[16];
        #pragma unroll
        for (int j = 0; j < 8; j++) {
            o[2 * j + 0] = __uint_as_float((unsigned)acc[i][j]) + bcol[2 * j + 0];
            o[2 * j + 1] = __uint_as_float((unsigned)(acc[i][j] >> 32)) + bcol[2 * j + 1];
        }
        if (relu) {
            #pragma unroll
            for (int j = 0; j < 16; j++) o[j] = fmaxf(o[j], 0.f);
        }
        if (gr < nrows) {
            *(float4*)(out + (size_t)gr * D + tc)      = make_float4(o[0], o[1], o[2], o[3]);
            *(float4*)(out + (size_t)gr * D + tc + 4)  = make_float4(o[4], o[5], o[6], o[7]);
            *(float4*)(out + (size_t)gr * D + tc + 8)  = make_float4(o[8], o[9], o[10], o[11]);
            *(float4*)(out + (size_t)gr * D + tc + 12) = make_float4(o[12], o[13], o[14], o[15]);
        }
        if (do_att) {
            float p1 = 0.f, p2 = 0.f, p3 = 0.f, p4 = 0.f;
            #pragma unroll
            for (int j = 0; j < 16; j++) {
                p1 = fmaf(o[j], v1s[j], p1);
                p2 = fmaf(o[j], v1d[j], p2);
                p3 = fmaf(o[j], v2s[j], p3);
                p4 = fmaf(o[j], v2d[j], p4);
            }
            #pragma unroll
            for (int m = 1; m < 8; m <<= 1) {
                p1 += __shfl_xor_sync(0xffffffffu, p1, m);
                p2 += __shfl_xor_sync(0xffffffffu, p2, m);
                p3 += __shfl_xor_sync(0xffffffffu, p3, m);
                p4 += __shfl_xor_sync(0xffffffffu, p4, m);
            }
            if ((tid & 7) == 0 && gr < nrows) {
                int node = attBase + gr;
                g_as1[node] = p1; g_ad1[node] = p2;
                g_as2[node] = p3; g_ad2[node] = p4;
            }
        }
    }
}

// ---------------- CSR pass 1: count edges per dst ----------------------------
__global__ void k_count(const void* __restrict__ idx, int dOff, int E,
                        int dAdd, int base) {
    int e = blockIdx.x * blockDim.x + threadIdx.x;
    if (e >= E) return;
    long long d; load_edge(idx, dOff, e, d);
    int di = (int)(d + dAdd) - base;
    if ((unsigned)di < (unsigned)HN) atomicAdd(&g_cnt[di], 1);
}

// ---------------- CSR pass 2: single-block exclusive scan --------------------
__global__ __launch_bounds__(1024) void k_scan() {
    __shared__ int wsum[32];
    int t = threadIdx.x, lane = t & 31, wid = t >> 5;
    int running = 0;
    for (int base = 0; base < HN; base += 1024) {
        int i = base + t;
        int v = (i < HN) ? g_cnt[i] : 0;
        int incl = v;
        #pragma unroll
        for (int o = 1; o < 32; o <<= 1) {
            int u = __shfl_up_sync(0xffffffffu, incl, o);
            if (lane >= o) incl += u;
        }
        if (lane == 31) wsum[wid] = incl;
        __syncthreads();
        if (wid == 0) {
            int s = wsum[lane];
            #pragma unroll
            for (int o = 1; o < 32; o <<= 1) {
                int u = __shfl_up_sync(0xffffffffu, s, o);
                if (lane >= o) s += u;
            }
            wsum[lane] = s;
        }
        __syncthreads();
        int woff = wid ? wsum[wid - 1] : 0;
        int excl = running + woff + incl - v;
        if (i < HN) { g_ptr[i] = excl; g_pos[i] = excl; }
        running += wsum[31];
        __syncthreads();
    }
    if (t == 0) g_ptr[HN] = running;
}

// ---------------- CSR pass 3: scatter (src, weight) --------------------------
__global__ void k_scatter(const void* __restrict__ idx, int sOff, int dOff, int E,
                          int sAdd, int dAdd, int base,
                          const float* __restrict__ as, const float* __restrict__ ad) {
    int e = blockIdx.x * blockDim.x + threadIdx.x;
    if (e >= E) return;
    long long s, d;
    load_edge(idx, sOff, e, s);
    load_edge(idx, dOff, e, d);
    int si = (int)(s + sAdd);
    int di = (int)(d + dAdd) - base;
    if ((unsigned)di >= (unsigned)HN) return;
    float w = __expf(lrelu(as[si] + ad[di + base]));
    int p = atomicAdd(&g_pos[di], 1);
    g_edge[p] = make_int2(si, __float_as_int(w));
}

// ---------------- aggregation: warp per dst, normalized output ---------------
__global__ void k_agg(int base, const float* __restrict__ as,
                      const float* __restrict__ ad, float* __restrict__ aggOut) {
    int i = (blockIdx.x * blockDim.x + threadIdx.x) >> 5;
    int lane = threadIdx.x & 31;
    if (i >= HN) return;
    int g = base + i;
    float w = __expf(lrelu(as[g] + ad[g]));        // self loop
    float denom = w;
    float4 xv = ((const float4*)g_x)[(size_t)g * 32 + lane];
    float4 acc = make_float4(xv.x * w, xv.y * w, xv.z * w, xv.w * w);
    int e0 = g_ptr[i], e1 = g_ptr[i + 1];
    for (int e = e0; e < e1; e++) {
        int2 ed = g_edge[e];
        float we = __int_as_float(ed.y);
        float4 xe = ((const float4*)g_x)[(size_t)ed.x * 32 + lane];
        acc.x = fmaf(xe.x, we, acc.x);
        acc.y = fmaf(xe.y, we, acc.y);
        acc.z = fmaf(xe.z, we, acc.z);
        acc.w = fmaf(xe.w, we, acc.w);
        denom += we;
    }
    float sc = 1.0f / (denom + 1e-16f);
    ((float4*)aggOut)[(size_t)i * 32 + lane] =
        make_float4(acc.x * sc, acc.y * sc, acc.z * sc, acc.w * sc);
}

// ---------------- driver ------------------------------------------------------
extern "C" void kernel_launch(void* const* d_in, const int* in_sizes, int n_in,
                              void* d_out, int out_size) {
    const void*  edge   = d_in[0];
    const void*  paper  = d_in[1];
    const void*  author = d_in[2];
    const float* x_s = (const float*)d_in[3];
    const float* x_t = (const float*)d_in[4];
    const float* Ws  = (const float*)d_in[5];
    const float* bs  = (const float*)d_in[6];
    const float* Wt  = (const float*)d_in[7];
    const float* bt  = (const float*)d_in[8];
    const float* W1  = (const float*)d_in[9];
    const float* a1s = (const float*)d_in[10];
    const float* a1d = (const float*)d_in[11];
    const float* W2  = (const float*)d_in[12];
    const float* a2s = (const float*)d_in[13];
    const float* a2d = (const float*)d_in[14];
    float* out = (float*)d_out;

    const int E0 = in_sizes[0] / 2;
    const int E1 = in_sizes[1] / 2;
    const int E2 = in_sizes[2] / 2;

    float* gx;    cudaGetSymbolAddress((void**)&gx,   g_x);
    float* gagg1; cudaGetSymbolAddress((void**)&gagg1, g_agg1);
    float* gagg2; cudaGetSymbolAddress((void**)&gagg2, g_agg2);
    float *gas1, *gad1, *gas2, *gad2;
    cudaGetSymbolAddress((void**)&gas1, g_as1);
    cudaGetSymbolAddress((void**)&gad1, g_ad1);
    cudaGetSymbolAddress((void**)&gas2, g_as2);
    cudaGetSymbolAddress((void**)&gad2, g_ad2);
    int* gcnt; cudaGetSymbolAddress((void**)&gcnt, g_cnt);

    const int GB = (NS + BM - 1) / BM;      // 391 blocks per 50K-row GEMM
    const int TB = 256;
    const int EB0 = (E0 + TB - 1) / TB;
    const int EB1 = (E1 + TB - 1) / TB;
    const int EB2 = (E2 + TB - 1) / TB;
    const int WNB = (HN * 32 + TB - 1) / TB;

    k_detect<<<1, 32>>>((const int*)edge);
    k_wvec<<<1, 128>>>(W1, a1s, a1d, W2, a2s, a2d);

    // fused input transforms + attention logits
    k_gemm2<<<2 * GB, 128>>>(x_s, Ws, bs, gx,
                             x_t, Wt, bt, gx + (size_t)NS * D,
                             GB, NS, NT, 0, 1);

    // ---- conv1: dst in [NS, NN) ----
    cudaMemsetAsync(gcnt, 0, HN * sizeof(int));
    k_count<<<EB0, TB>>>(edge,   E0, E0, NS, NS);
    k_count<<<EB2, TB>>>(author, E2, E2, 0,  NS);
    k_scan<<<1, 1024>>>();
    k_scatter<<<EB0, TB>>>(edge,   0, E0, E0, 0, NS, NS, gas1, gad1);
    k_scatter<<<EB2, TB>>>(author, 0, E2, E2, 0, 0,  NS, gas1, gad1);
    k_agg<<<WNB, TB>>>(NS, gas1, gad1, gagg1);

    // ---- conv2: dst in [0, NS) ----
    cudaMemsetAsync(gcnt, 0, HN * sizeof(int));
    k_count<<<EB0, TB>>>(edge,  0,  E0, 0, 0);
    k_count<<<EB1, TB>>>(paper, E1, E1, 0, 0);
    k_scan<<<1, 1024>>>();
    k_scatter<<<EB0, TB>>>(edge,  E0, 0,  E0, NS, 0, 0, gas2, gad2);
    k_scatter<<<EB1, TB>>>(paper, 0,  E1, E1, 0,  0, 0, gas2, gad2);
    k_agg<<<WNB, TB>>>(0, gas2, gad2, gagg2);

    // fused output GEMMs
    k_gemm2<<<2 * GB, 128>>>(gagg1, W1, nullptr, out + (size_t)NS * D,
                             gagg2, W2, nullptr, out,
                             GB, NS, NS, 1, 0);
}

// round 14
// speedup vs baseline: 1.2031x; 1.2022x over previous
#include <cuda_runtime.h>

#define NS   50000
#define NT   50000
#define NN   100000
#define D    128
#define NEG  0.2f

#define BM   128
#define BK   16
#define EMAX 2100000

// ---------------- scratch (device globals) ----------------------------------
__device__ float g_x[(size_t)NN * D];
__device__ float g_agg[(size_t)NN * D];
__device__ float g_as1[NN], g_ad1[NN], g_as2[NN], g_ad2[NN];
__device__ float g_w1s[D], g_w1d[D], g_w2s[D], g_w2d[D];
__device__ int   g_cnt[NN];
__device__ int   g_ptr[NN + 1];
__device__ int   g_pos[NN];
__device__ int2  g_edge[EMAX];
__device__ int   g_is64;

__device__ __forceinline__ float lrelu(float v) { return v >= 0.f ? v : NEG * v; }

__device__ __forceinline__ void ffma2(unsigned long long& acc,
                                      unsigned long long a, unsigned long long b) {
    asm("fma.rn.f32x2 %0, %1, %2, %0;" : "+l"(acc) : "l"(a), "l"(b));
}
__device__ __forceinline__ unsigned long long dup2(float a) {
    unsigned long long r;
    asm("mov.b64 %0, {%1, %1};" : "=l"(r) : "r"(__float_as_uint(a)));
    return r;
}

// ---------------- index width detection -------------------------------------
__global__ void k_detect(const int* __restrict__ p) {
    if (threadIdx.x == 0) {
        int all0 = 1;
        #pragma unroll
        for (int i = 1; i < 128; i += 2) all0 &= (p[i] == 0);
        g_is64 = all0;
    }
}

__device__ __forceinline__ long long eidx(const void* idx, int off, int e) {
    return g_is64 ? ((const long long*)idx)[off + e]
                  : (long long)((const int*)idx)[off + e];
}

// ---------------- wv = W^T @ a ----------------------------------------------
__global__ void k_wvec(const float* __restrict__ W1, const float* __restrict__ a1s,
                       const float* __restrict__ a1d,
                       const float* __restrict__ W2, const float* __restrict__ a2s,
                       const float* __restrict__ a2d) {
    int j = threadIdx.x;
    float s1 = 0.f, d1 = 0.f, s2 = 0.f, d2 = 0.f;
    for (int k = 0; k < D; k++) {
        float w1 = W1[k * D + j], w2 = W2[k * D + j];
        s1 = fmaf(w1, a1s[k], s1); d1 = fmaf(w1, a1d[k], d1);
        s2 = fmaf(w2, a2s[k], s2); d2 = fmaf(w2, a2d[k], d2);
    }
    g_w1s[j] = s1; g_w1d[j] = d1; g_w2s[j] = s2; g_w2d[j] = d2;
}

// ---------------- dual register-tiled SGEMM (f32x2, 8x8 tile, R10 shape) -----
// out[r,c] = act(bias[c] + in[r] . W[c,:]); optional fused attention logits.
__global__ __launch_bounds__(256, 2) void k_gemm2(
    const float* __restrict__ inA, const float* __restrict__ WA,
    const float* __restrict__ biasA, float* __restrict__ outA,
    const float* __restrict__ inB, const float* __restrict__ WB,
    const float* __restrict__ biasB, float* __restrict__ outB,
    int split, int rowsA, int rowsB, int relu, int do_att)
{
    __shared__ float As[BK][BM];
    __shared__ float Bs[BK][128];

    const float *in, *W, *bias; float* out; int row0, nrows, attBase;
    if ((int)blockIdx.x < split) {
        in = inA; W = WA; bias = biasA; out = outA;
        row0 = blockIdx.x * BM; nrows = rowsA; attBase = 0;
    } else {
        in = inB; W = WB; bias = biasB; out = outB;
        row0 = (blockIdx.x - split) * BM; nrows = rowsB; attBase = NS;
    }

    const int tid = threadIdx.x;
    const int tr  = (tid >> 4) << 3;
    const int tc  = (tid & 15) << 3;

    unsigned long long acc[8][4];
    #pragma unroll
    for (int i = 0; i < 8; i++)
        #pragma unroll
        for (int j = 0; j < 4; j++) acc[i][j] = 0ull;

    for (int k0 = 0; k0 < D; k0 += BK) {
        __syncthreads();
        #pragma unroll
        for (int i = 0; i < 2; i++) {
            int lin = i * 256 + tid;
            int r   = lin >> 2;
            int jj  = (lin & 3) << 2;
            int gr  = row0 + r;
            float4 v = make_float4(0.f, 0.f, 0.f, 0.f);
            if (gr < nrows) v = *(const float4*)(in + (size_t)gr * D + k0 + jj);
            As[jj + 0][r] = v.x; As[jj + 1][r] = v.y;
            As[jj + 2][r] = v.z; As[jj + 3][r] = v.w;
            float4 w = *(const float4*)(W + (size_t)r * D + k0 + jj);
            Bs[jj + 0][r] = w.x; Bs[jj + 1][r] = w.y;
            Bs[jj + 2][r] = w.z; Bs[jj + 3][r] = w.w;
        }
        __syncthreads();

        #pragma unroll
        for (int kk = 0; kk < BK; kk++) {
            float4 a0 = *(const float4*)&As[kk][tr];
            float4 a1 = *(const float4*)&As[kk][tr + 4];
            ulonglong2 w0 = *(const ulonglong2*)&Bs[kk][tc];
            ulonglong2 w1 = *(const ulonglong2*)&Bs[kk][tc + 4];
            float a[8] = {a0.x, a0.y, a0.z, a0.w, a1.x, a1.y, a1.z, a1.w};
            #pragma unroll
            for (int i = 0; i < 8; i++) {
                unsigned long long ap = dup2(a[i]);
                ffma2(acc[i][0], ap, w0.x);
                ffma2(acc[i][1], ap, w0.y);
                ffma2(acc[i][2], ap, w1.x);
                ffma2(acc[i][3], ap, w1.y);
            }
        }
    }

    float bcol[8];
    #pragma unroll
    for (int j = 0; j < 8; j++) bcol[j] = bias ? bias[tc + j] : 0.f;

    #pragma unroll
    for (int i = 0; i < 8; i++) {
        int gr = row0 + tr + i;
        float o[8];
        #pragma unroll
        for (int j = 0; j < 4; j++) {
            o[2 * j + 0] = __uint_as_float((unsigned)acc[i][j]) + bcol[2 * j + 0];
            o[2 * j + 1] = __uint_as_float((unsigned)(acc[i][j] >> 32)) + bcol[2 * j + 1];
        }
        if (relu) {
            #pragma unroll
            for (int j = 0; j < 8; j++) o[j] = fmaxf(o[j], 0.f);
        }
        if (gr < nrows) {
            *(float4*)(out + (size_t)gr * D + tc)     = make_float4(o[0], o[1], o[2], o[3]);
            *(float4*)(out + (size_t)gr * D + tc + 4) = make_float4(o[4], o[5], o[6], o[7]);
        }
        if (do_att) {
            float p1 = 0.f, p2 = 0.f, p3 = 0.f, p4 = 0.f;
            #pragma unroll
            for (int j = 0; j < 8; j++) {
                float ov = o[j];
                p1 = fmaf(ov, g_w1s[tc + j], p1);
                p2 = fmaf(ov, g_w1d[tc + j], p2);
                p3 = fmaf(ov, g_w2s[tc + j], p3);
                p4 = fmaf(ov, g_w2d[tc + j], p4);
            }
            #pragma unroll
            for (int m = 1; m < 16; m <<= 1) {      // reduce over 16 col-threads
                p1 += __shfl_xor_sync(0xffffffffu, p1, m);
                p2 += __shfl_xor_sync(0xffffffffu, p2, m);
                p3 += __shfl_xor_sync(0xffffffffu, p3, m);
                p4 += __shfl_xor_sync(0xffffffffu, p4, m);
            }
            if ((tid & 15) == 0 && gr < nrows) {
                int node = attBase + gr;
                g_as1[node] = p1; g_ad1[node] = p2;
                g_as2[node] = p3; g_ad2[node] = p4;
            }
        }
    }
}

// ---------------- CSR count: bipartite list feeds BOTH convs -----------------
__global__ void k_count_bi(const void* __restrict__ idx, int E) {
    int e = blockIdx.x * blockDim.x + threadIdx.x;
    if (e >= E) return;
    int s = (int)eidx(idx, 0, e);            // paper id  (conv2 dst)
    int d = (int)eidx(idx, E, e) + NS;       // author id (conv1 dst)
    atomicAdd(&g_cnt[d], 1);
    atomicAdd(&g_cnt[s], 1);
}

// generic list: bucket = dst, only when dst in [lo, hi)
__global__ void k_count_g(const void* __restrict__ idx, int E, int lo, int hi) {
    int e = blockIdx.x * blockDim.x + threadIdx.x;
    if (e >= E) return;
    int d = (int)eidx(idx, E, e);
    if (d >= lo && d < hi) atomicAdd(&g_cnt[d], 1);
}

// ---------------- CSR scan: single-block exclusive scan over NN --------------
__global__ __launch_bounds__(1024) void k_scan() {
    __shared__ int wsum[32];
    int t = threadIdx.x, lane = t & 31, wid = t >> 5;
    int running = 0;
    for (int base = 0; base < NN; base += 1024) {
        int i = base + t;
        int v = (i < NN) ? g_cnt[i] : 0;
        int incl = v;
        #pragma unroll
        for (int o = 1; o < 32; o <<= 1) {
            int u = __shfl_up_sync(0xffffffffu, incl, o);
            if (lane >= o) incl += u;
        }
        if (lane == 31) wsum[wid] = incl;
        __syncthreads();
        if (wid == 0) {
            int s = wsum[lane];
            #pragma unroll
            for (int o = 1; o < 32; o <<= 1) {
                int u = __shfl_up_sync(0xffffffffu, s, o);
                if (lane >= o) s += u;
            }
            wsum[lane] = s;
        }
        __syncthreads();
        int woff = wid ? wsum[wid - 1] : 0;
        int excl = running + woff + incl - v;
        if (i < NN) { g_ptr[i] = excl; g_pos[i] = excl; }
        running += wsum[31];
        __syncthreads();
    }
    if (t == 0) g_ptr[NN] = running;
}

// ---------------- CSR scatter ------------------------------------------------
__global__ void k_scat_bi(const void* __restrict__ idx, int E) {
    int e = blockIdx.x * blockDim.x + threadIdx.x;
    if (e >= E) return;
    int s = (int)eidx(idx, 0, e);             // paper node
    int d = (int)eidx(idx, E, e) + NS;        // author node
    // conv1 record: src=s, dst=d, weights (as1, ad1)
    float w1 = __expf(lrelu(g_as1[s] + g_ad1[d]));
    int p1 = atomicAdd(&g_pos[d], 1);
    g_edge[p1] = make_int2(s, __float_as_int(w1));
    // conv2 record: src=d, dst=s, weights (as2, ad2)
    float w2 = __expf(lrelu(g_as2[d] + g_ad2[s]));
    int p2 = atomicAdd(&g_pos[s], 1);
    g_edge[p2] = make_int2(d, __float_as_int(w2));
}

__global__ void k_scat_g(const void* __restrict__ idx, int E, int lo, int hi,
                         const float* __restrict__ as, const float* __restrict__ ad) {
    int e = blockIdx.x * blockDim.x + threadIdx.x;
    if (e >= E) return;
    int d = (int)eidx(idx, E, e);
    if (d < lo || d >= hi) return;
    int s = (int)eidx(idx, 0, e);
    float w = __expf(lrelu(as[s] + ad[d]));
    int p = atomicAdd(&g_pos[d], 1);
    g_edge[p] = make_int2(s, __float_as_int(w));
}

// ---------------- aggregation: warp per dst over all NN nodes ----------------
__global__ void k_agg() {
    int i = (blockIdx.x * blockDim.x + threadIdx.x) >> 5;
    int lane = threadIdx.x & 31;
    if (i >= NN) return;
    // self loop: conv2 vectors for papers (<NS), conv1 vectors for authors
    float w = (i < NS) ? __expf(lrelu(g_as2[i] + g_ad2[i]))
                       : __expf(lrelu(g_as1[i] + g_ad1[i]));
    float denom = w;
    float4 xv = ((const float4*)g_x)[(size_t)i * 32 + lane];
    float4 acc = make_float4(xv.x * w, xv.y * w, xv.z * w, xv.w * w);
    int e0 = g_ptr[i], e1 = g_ptr[i + 1];
    for (int e = e0; e < e1; e++) {
        int2 ed = g_edge[e];
        float we = __int_as_float(ed.y);
        float4 xe = ((const float4*)g_x)[(size_t)ed.x * 32 + lane];
        acc.x = fmaf(xe.x, we, acc.x);
        acc.y = fmaf(xe.y, we, acc.y);
        acc.z = fmaf(xe.z, we, acc.z);
        acc.w = fmaf(xe.w, we, acc.w);
        denom += we;
    }
    float sc = 1.0f / (denom + 1e-16f);
    ((float4*)g_agg)[(size_t)i * 32 + lane] =
        make_float4(acc.x * sc, acc.y * sc, acc.z * sc, acc.w * sc);
}

// ---------------- driver ------------------------------------------------------
extern "C" void kernel_launch(void* const* d_in, const int* in_sizes, int n_in,
                              void* d_out, int out_size) {
    const void*  edge   = d_in[0];
    const void*  paper  = d_in[1];
    const void*  author = d_in[2];
    const float* x_s = (const float*)d_in[3];
    const float* x_t = (const float*)d_in[4];
    const float* Ws  = (const float*)d_in[5];
    const float* bs  = (const float*)d_in[6];
    const float* Wt  = (const float*)d_in[7];
    const float* bt  = (const float*)d_in[8];
    const float* W1  = (const float*)d_in[9];
    const float* a1s = (const float*)d_in[10];
    const float* a1d = (const float*)d_in[11];
    const float* W2  = (const float*)d_in[12];
    const float* a2s = (const float*)d_in[13];
    const float* a2d = (const float*)d_in[14];
    float* out = (float*)d_out;

    const int E0 = in_sizes[0] / 2;
    const int E1 = in_sizes[1] / 2;
    const int E2 = in_sizes[2] / 2;

    float* gx;   cudaGetSymbolAddress((void**)&gx,   g_x);
    float* gagg; cudaGetSymbolAddress((void**)&gagg, g_agg);
    float *gas1, *gad1, *gas2, *gad2;
    cudaGetSymbolAddress((void**)&gas1, g_as1);
    cudaGetSymbolAddress((void**)&gad1, g_ad1);
    cudaGetSymbolAddress((void**)&gas2, g_as2);
    cudaGetSymbolAddress((void**)&gad2, g_ad2);
    int* gcnt; cudaGetSymbolAddress((void**)&gcnt, g_cnt);

    const int GB = (NS + BM - 1) / BM;      // 391 blocks per 50K-row problem
    const int TB = 256;
    const int EB0 = (E0 + TB - 1) / TB;
    const int EB1 = (E1 + TB - 1) / TB;
    const int EB2 = (E2 + TB - 1) / TB;
    const int WNB = (NN * 32 + TB - 1) / TB;

    k_detect<<<1, 32>>>((const int*)edge);
    k_wvec<<<1, 128>>>(W1, a1s, a1d, W2, a2s, a2d);

    // fused input transforms + attention logits
    k_gemm2<<<2 * GB, 256>>>(x_s, Ws, bs, gx,
                             x_t, Wt, bt, gx + (size_t)NS * D,
                             GB, NS, NT, 0, 1);

    // ---- combined CSR over all NN dst nodes ----
    cudaMemsetAsync(gcnt, 0, NN * sizeof(int));
    k_count_bi<<<EB0, TB>>>(edge, E0);
    k_count_g<<<EB2, TB>>>(author, E2, NS, NN);   // conv1 region
    k_count_g<<<EB1, TB>>>(paper,  E1, 0,  NS);   // conv2 region
    k_scan<<<1, 1024>>>();
    k_scat_bi<<<EB0, TB>>>(edge, E0);
    k_scat_g<<<EB2, TB>>>(author, E2, NS, NN, gas1, gad1);
    k_scat_g<<<EB1, TB>>>(paper,  E1, 0,  NS, gas2, gad2);
    k_agg<<<WNB, TB>>>();

    // fused output GEMMs: out[NS:] = relu(agg[NS:]@W1^T), out[:NS] = relu(agg[:NS]@W2^T)
    k_gemm2<<<2 * GB, 256>>>(gagg + (size_t)NS * D, W1, nullptr, out + (size_t)NS * D,
                             gagg, W2, nullptr, out,
                             GB, NS, NS, 1, 0);
}

// round 15
// speedup vs baseline: 1.3013x; 1.0816x over previous
#include <cuda_runtime.h>
#include <cuda_fp16.h>

#define NS   50000
#define NT   50000
#define NN   100000
#define D    128
#define NEG  0.2f

#define BM   128
#define BK   16
#define EMAX 2100000

// ---------------- scratch (device globals) ----------------------------------
__device__ __half g_xh[(size_t)NN * D];     // fp16 transformed features (25.6MB)
__device__ __half g_aggh[(size_t)NN * D];   // fp16 aggregated features
__device__ float  g_as1[NN], g_ad1[NN], g_as2[NN], g_ad2[NN];
__device__ float  g_w1s[D], g_w1d[D], g_w2s[D], g_w2d[D];
__device__ int    g_cnt[NN];
__device__ int    g_ptr[NN + 1];
__device__ int    g_pos[NN];
__device__ int2   g_edge[EMAX];
__device__ int    g_is64;

__device__ __forceinline__ float lrelu(float v) { return v >= 0.f ? v : NEG * v; }

__device__ __forceinline__ void ffma2(unsigned long long& acc,
                                      unsigned long long a, unsigned long long b) {
    asm("fma.rn.f32x2 %0, %1, %2, %0;" : "+l"(acc) : "l"(a), "l"(b));
}
__device__ __forceinline__ unsigned long long dup2(float a) {
    unsigned long long r;
    asm("mov.b64 %0, {%1, %1};" : "=l"(r) : "r"(__float_as_uint(a)));
    return r;
}

// ---------------- index width detection -------------------------------------
__global__ void k_detect(const int* __restrict__ p) {
    if (threadIdx.x == 0) {
        int all0 = 1;
        #pragma unroll
        for (int i = 1; i < 128; i += 2) all0 &= (p[i] == 0);
        g_is64 = all0;
    }
}

__device__ __forceinline__ int eidx(const void* idx, int off, int e) {
    return g_is64 ? (int)((const long long*)idx)[off + e]
                  : ((const int*)idx)[off + e];
}

// ---------------- wv = W^T @ a ----------------------------------------------
__global__ void k_wvec(const float* __restrict__ W1, const float* __restrict__ a1s,
                       const float* __restrict__ a1d,
                       const float* __restrict__ W2, const float* __restrict__ a2s,
                       const float* __restrict__ a2d) {
    int j = threadIdx.x;
    float s1 = 0.f, d1 = 0.f, s2 = 0.f, d2 = 0.f;
    for (int k = 0; k < D; k++) {
        float w1 = W1[k * D + j], w2 = W2[k * D + j];
        s1 = fmaf(w1, a1s[k], s1); d1 = fmaf(w1, a1d[k], d1);
        s2 = fmaf(w2, a2s[k], s2); d2 = fmaf(w2, a2d[k], d2);
    }
    g_w1s[j] = s1; g_w1d[j] = d1; g_w2s[j] = s2; g_w2d[j] = d2;
}

// ---------------- dual register-tiled SGEMM (f32x2, 8x8 tile) ----------------
// out[r,c] = act(bias[c] + in[r] . W[c,:]); A input fp32 or fp16; output fp32
// or fp16; optional fused attention logits (for fp16-out pass).
__global__ __launch_bounds__(256, 2) void k_gemm2(
    const void* __restrict__ inA, const float* __restrict__ WA,
    const float* __restrict__ biasA, void* __restrict__ outA,
    const void* __restrict__ inB, const float* __restrict__ WB,
    const float* __restrict__ biasB, void* __restrict__ outB,
    int split, int rowsA, int rowsB, int relu, int do_att,
    int in_half, int out_half)
{
    __shared__ float As[BK][BM];
    __shared__ float Bs[BK][128];

    const void *in; const float *W, *bias; void* out; int row0, nrows, attBase;
    if ((int)blockIdx.x < split) {
        in = inA; W = WA; bias = biasA; out = outA;
        row0 = blockIdx.x * BM; nrows = rowsA; attBase = 0;
    } else {
        in = inB; W = WB; bias = biasB; out = outB;
        row0 = (blockIdx.x - split) * BM; nrows = rowsB; attBase = NS;
    }

    const int tid = threadIdx.x;
    const int tr  = (tid >> 4) << 3;
    const int tc  = (tid & 15) << 3;

    unsigned long long acc[8][4];
    #pragma unroll
    for (int i = 0; i < 8; i++)
        #pragma unroll
        for (int j = 0; j < 4; j++) acc[i][j] = 0ull;

    for (int k0 = 0; k0 < D; k0 += BK) {
        __syncthreads();
        #pragma unroll
        for (int i = 0; i < 2; i++) {
            int lin = i * 256 + tid;
            int r   = lin >> 2;
            int jj  = (lin & 3) << 2;
            int gr  = row0 + r;
            float4 v = make_float4(0.f, 0.f, 0.f, 0.f);
            if (gr < nrows) {
                if (in_half) {
                    const __half* inh = (const __half*)in;
                    uint2 u = *(const uint2*)(inh + (size_t)gr * D + k0 + jj);
                    float2 f0 = __half22float2(*reinterpret_cast<const __half2*>(&u.x));
                    float2 f1 = __half22float2(*reinterpret_cast<const __half2*>(&u.y));
                    v = make_float4(f0.x, f0.y, f1.x, f1.y);
                } else {
                    v = *(const float4*)((const float*)in + (size_t)gr * D + k0 + jj);
                }
            }
            As[jj + 0][r] = v.x; As[jj + 1][r] = v.y;
            As[jj + 2][r] = v.z; As[jj + 3][r] = v.w;
            float4 w = *(const float4*)(W + (size_t)r * D + k0 + jj);
            Bs[jj + 0][r] = w.x; Bs[jj + 1][r] = w.y;
            Bs[jj + 2][r] = w.z; Bs[jj + 3][r] = w.w;
        }
        __syncthreads();

        #pragma unroll
        for (int kk = 0; kk < BK; kk++) {
            float4 a0 = *(const float4*)&As[kk][tr];
            float4 a1 = *(const float4*)&As[kk][tr + 4];
            ulonglong2 w0 = *(const ulonglong2*)&Bs[kk][tc];
            ulonglong2 w1 = *(const ulonglong2*)&Bs[kk][tc + 4];
            float a[8] = {a0.x, a0.y, a0.z, a0.w, a1.x, a1.y, a1.z, a1.w};
            #pragma unroll
            for (int i = 0; i < 8; i++) {
                unsigned long long ap = dup2(a[i]);
                ffma2(acc[i][0], ap, w0.x);
                ffma2(acc[i][1], ap, w0.y);
                ffma2(acc[i][2], ap, w1.x);
                ffma2(acc[i][3], ap, w1.y);
            }
        }
    }

    float bcol[8];
    #pragma unroll
    for (int j = 0; j < 8; j++) bcol[j] = bias ? bias[tc + j] : 0.f;

    #pragma unroll
    for (int i = 0; i < 8; i++) {
        int gr = row0 + tr + i;
        float o[8];
        #pragma unroll
        for (int j = 0; j < 4; j++) {
            o[2 * j + 0] = __uint_as_float((unsigned)acc[i][j]) + bcol[2 * j + 0];
            o[2 * j + 1] = __uint_as_float((unsigned)(acc[i][j] >> 32)) + bcol[2 * j + 1];
        }
        if (relu) {
            #pragma unroll
            for (int j = 0; j < 8; j++) o[j] = fmaxf(o[j], 0.f);
        }
        if (gr < nrows) {
            if (out_half) {
                __half h[8];
                #pragma unroll
                for (int j = 0; j < 8; j++) h[j] = __float2half_rn(o[j]);
                *(uint4*)((__half*)out + (size_t)gr * D + tc) = *(uint4*)h;
            } else {
                *(float4*)((float*)out + (size_t)gr * D + tc)     = make_float4(o[0], o[1], o[2], o[3]);
                *(float4*)((float*)out + (size_t)gr * D + tc + 4) = make_float4(o[4], o[5], o[6], o[7]);
            }
        }
        if (do_att) {
            float p1 = 0.f, p2 = 0.f, p3 = 0.f, p4 = 0.f;
            #pragma unroll
            for (int j = 0; j < 8; j++) {
                float ov = o[j];
                p1 = fmaf(ov, g_w1s[tc + j], p1);
                p2 = fmaf(ov, g_w1d[tc + j], p2);
                p3 = fmaf(ov, g_w2s[tc + j], p3);
                p4 = fmaf(ov, g_w2d[tc + j], p4);
            }
            #pragma unroll
            for (int m = 1; m < 16; m <<= 1) {
                p1 += __shfl_xor_sync(0xffffffffu, p1, m);
                p2 += __shfl_xor_sync(0xffffffffu, p2, m);
                p3 += __shfl_xor_sync(0xffffffffu, p3, m);
                p4 += __shfl_xor_sync(0xffffffffu, p4, m);
            }
            if ((tid & 15) == 0 && gr < nrows) {
                int node = attBase + gr;
                g_as1[node] = p1; g_ad1[node] = p2;
                g_as2[node] = p3; g_ad2[node] = p4;
            }
        }
    }
}

// ---------------- fused CSR count over all three edge lists ------------------
__global__ void k_count_all(const void* __restrict__ e0, const void* __restrict__ e1,
                            const void* __restrict__ e2, int E0, int E1, int E2) {
    int t = blockIdx.x * blockDim.x + threadIdx.x;
    if (t < E0) {
        int s = eidx(e0, 0, t);             // paper (conv2 dst)
        int d = eidx(e0, E0, t) + NS;       // author (conv1 dst)
        atomicAdd(&g_cnt[d], 1);
        atomicAdd(&g_cnt[s], 1);
    } else if (t < E0 + E1) {
        int e = t - E0;
        int d = eidx(e1, E1, e);
        if ((unsigned)d < (unsigned)NS) atomicAdd(&g_cnt[d], 1);
    } else if (t < E0 + E1 + E2) {
        int e = t - E0 - E1;
        int d = eidx(e2, E2, e);
        if (d >= NS && d < NN) atomicAdd(&g_cnt[d], 1);
    }
}

// ---------------- CSR scan: single-block exclusive scan over NN --------------
__global__ __launch_bounds__(1024) void k_scan() {
    __shared__ int wsum[32];
    int t = threadIdx.x, lane = t & 31, wid = t >> 5;
    int running = 0;
    for (int base = 0; base < NN; base += 1024) {
        int i = base + t;
        int v = (i < NN) ? g_cnt[i] : 0;
        int incl = v;
        #pragma unroll
        for (int o = 1; o < 32; o <<= 1) {
            int u = __shfl_up_sync(0xffffffffu, incl, o);
            if (lane >= o) incl += u;
        }
        if (lane == 31) wsum[wid] = incl;
        __syncthreads();
        if (wid == 0) {
            int s = wsum[lane];
            #pragma unroll
            for (int o = 1; o < 32; o <<= 1) {
                int u = __shfl_up_sync(0xffffffffu, s, o);
                if (lane >= o) s += u;
            }
            wsum[lane] = s;
        }
        __syncthreads();
        int woff = wid ? wsum[wid - 1] : 0;
        int excl = running + woff + incl - v;
        if (i < NN) { g_ptr[i] = excl; g_pos[i] = excl; }
        running += wsum[31];
        __syncthreads();
    }
    if (t == 0) g_ptr[NN] = running;
}

// ---------------- fused CSR scatter ------------------------------------------
__global__ void k_scat_all(const void* __restrict__ e0, const void* __restrict__ e1,
                           const void* __restrict__ e2, int E0, int E1, int E2) {
    int t = blockIdx.x * blockDim.x + threadIdx.x;
    if (t < E0) {
        int s = eidx(e0, 0, t);
        int d = eidx(e0, E0, t) + NS;
        float w1 = __expf(lrelu(g_as1[s] + g_ad1[d]));
        int p1 = atomicAdd(&g_pos[d], 1);
        g_edge[p1] = make_int2(s, __float_as_int(w1));
        float w2 = __expf(lrelu(g_as2[d] + g_ad2[s]));
        int p2 = atomicAdd(&g_pos[s], 1);
        g_edge[p2] = make_int2(d, __float_as_int(w2));
    } else if (t < E0 + E1) {
        int e = t - E0;
        int d = eidx(e1, E1, e);
        if ((unsigned)d >= (unsigned)NS) return;
        int s = eidx(e1, 0, e);
        float w = __expf(lrelu(g_as2[s] + g_ad2[d]));
        int p = atomicAdd(&g_pos[d], 1);
        g_edge[p] = make_int2(s, __float_as_int(w));
    } else if (t < E0 + E1 + E2) {
        int e = t - E0 - E1;
        int d = eidx(e2, E2, e);
        if (d < NS || d >= NN) return;
        int s = eidx(e2, 0, e);
        float w = __expf(lrelu(g_as1[s] + g_ad1[d]));
        int p = atomicAdd(&g_pos[d], 1);
        g_edge[p] = make_int2(s, __float_as_int(w));
    }
}

// ---------------- aggregation: warp per dst, fp16 gather, fp32 accum ---------
__global__ void k_agg() {
    int i = (blockIdx.x * blockDim.x + threadIdx.x) >> 5;
    int lane = threadIdx.x & 31;
    if (i >= NN) return;
    float w = (i < NS) ? __expf(lrelu(g_as2[i] + g_ad2[i]))
                       : __expf(lrelu(g_as1[i] + g_ad1[i]));
    float denom = w;
    const uint2* xh = (const uint2*)g_xh;     // 4 halfs per lane
    uint2 u = xh[(size_t)i * 32 + lane];
    float2 f0 = __half22float2(*reinterpret_cast<const __half2*>(&u.x));
    float2 f1 = __half22float2(*reinterpret_cast<const __half2*>(&u.y));
    float4 acc = make_float4(f0.x * w, f0.y * w, f1.x * w, f1.y * w);
    int e0 = g_ptr[i], e1 = g_ptr[i + 1];
    for (int e = e0; e < e1; e++) {
        int2 ed = g_edge[e];
        float we = __int_as_float(ed.y);
        uint2 ue = xh[(size_t)ed.x * 32 + lane];
        float2 g0 = __half22float2(*reinterpret_cast<const __half2*>(&ue.x));
        float2 g1 = __half22float2(*reinterpret_cast<const __half2*>(&ue.y));
        acc.x = fmaf(g0.x, we, acc.x);
        acc.y = fmaf(g0.y, we, acc.y);
        acc.z = fmaf(g1.x, we, acc.z);
        acc.w = fmaf(g1.y, we, acc.w);
        denom += we;
    }
    float sc = 1.0f / (denom + 1e-16f);
    __half2 h0 = __floats2half2_rn(acc.x * sc, acc.y * sc);
    __half2 h1 = __floats2half2_rn(acc.z * sc, acc.w * sc);
    uint2 o;
    o.x = *reinterpret_cast<unsigned*>(&h0);
    o.y = *reinterpret_cast<unsigned*>(&h1);
    ((uint2*)g_aggh)[(size_t)i * 32 + lane] = o;
}

// ---------------- driver ------------------------------------------------------
extern "C" void kernel_launch(void* const* d_in, const int* in_sizes, int n_in,
                              void* d_out, int out_size) {
    const void*  edge   = d_in[0];
    const void*  paper  = d_in[1];
    const void*  author = d_in[2];
    const float* x_s = (const float*)d_in[3];
    const float* x_t = (const float*)d_in[4];
    const float* Ws  = (const float*)d_in[5];
    const float* bs  = (const float*)d_in[6];
    const float* Wt  = (const float*)d_in[7];
    const float* bt  = (const float*)d_in[8];
    const float* W1  = (const float*)d_in[9];
    const float* a1s = (const float*)d_in[10];
    const float* a1d = (const float*)d_in[11];
    const float* W2  = (const float*)d_in[12];
    const float* a2s = (const float*)d_in[13];
    const float* a2d = (const float*)d_in[14];
    float* out = (float*)d_out;

    const int E0 = in_sizes[0] / 2;
    const int E1 = in_sizes[1] / 2;
    const int E2 = in_sizes[2] / 2;

    __half* gxh;  cudaGetSymbolAddress((void**)&gxh,  g_xh);
    __half* gah;  cudaGetSymbolAddress((void**)&gah,  g_aggh);
    int* gcnt;    cudaGetSymbolAddress((void**)&gcnt, g_cnt);

    const int GB = (NS + BM - 1) / BM;      // 391 blocks per 50K-row problem
    const int TB = 256;
    const int ET = E0 + E1 + E2;
    const int EBA = (ET + TB - 1) / TB;
    const int WNB = (NN * 32 + TB - 1) / TB;

    k_detect<<<1, 32>>>((const int*)edge);
    k_wvec<<<1, 128>>>(W1, a1s, a1d, W2, a2s, a2d);

    // fused input transforms (fp16 out) + attention logits
    k_gemm2<<<2 * GB, 256>>>(x_s, Ws, bs, gxh,
                             x_t, Wt, bt, gxh + (size_t)NS * D,
                             GB, NS, NT, 0, 1, 0, 1);

    // ---- combined CSR over all NN dst nodes ----
    cudaMemsetAsync(gcnt, 0, NN * sizeof(int));
    k_count_all<<<EBA, TB>>>(edge, paper, author, E0, E1, E2);
    k_scan<<<1, 1024>>>();
    k_scat_all<<<EBA, TB>>>(edge, paper, author, E0, E1, E2);
    k_agg<<<WNB, TB>>>();

    // fused output GEMMs (fp16 in, fp32 out + relu)
    k_gemm2<<<2 * GB, 256>>>(gah + (size_t)NS * D, W1, nullptr, out + (size_t)NS * D,
                             gah, W2, nullptr, out,
                             GB, NS, NS, 1, 0, 1, 0);
}

// round 16
// speedup vs baseline: 1.3131x; 1.0091x over previous
#include <cuda_runtime.h>
#include <cuda_fp16.h>

#define NS   50000
#define NT   50000
#define NN   100000
#define D    128
#define NEG  0.2f

#define BM   128
#define BK   16
#define EMAX 2100000

// ---------------- scratch (device globals) ----------------------------------
__device__ __half g_xh[(size_t)NN * D];     // fp16 transformed features (25.6MB)
__device__ __half g_aggh[(size_t)NN * D];   // fp16 aggregated features
__device__ float  g_as1[NN], g_ad1[NN], g_as2[NN], g_ad2[NN];
__device__ float  g_w1s[D], g_w1d[D], g_w2s[D], g_w2d[D];
__device__ int    g_cnt[NN];
__device__ int    g_ptr[NN + 1];
__device__ int    g_pos[NN];
__device__ int2   g_edge[EMAX];
__device__ int    g_is64;

__device__ __forceinline__ float lrelu(float v) { return v >= 0.f ? v : NEG * v; }

__device__ __forceinline__ void ffma2(unsigned long long& acc,
                                      unsigned long long a, unsigned long long b) {
    asm("fma.rn.f32x2 %0, %1, %2, %0;" : "+l"(acc) : "l"(a), "l"(b));
}
__device__ __forceinline__ unsigned long long dup2(float a) {
    unsigned long long r;
    asm("mov.b64 %0, {%1, %1};" : "=l"(r) : "r"(__float_as_uint(a)));
    return r;
}

// ---------------- index width detection -------------------------------------
__global__ void k_detect(const int* __restrict__ p) {
    if (threadIdx.x == 0) {
        int all0 = 1;
        #pragma unroll
        for (int i = 1; i < 128; i += 2) all0 &= (p[i] == 0);
        g_is64 = all0;
    }
}

__device__ __forceinline__ int eidx(const void* idx, int off, int e) {
    return g_is64 ? (int)((const long long*)idx)[off + e]
                  : ((const int*)idx)[off + e];
}

// ---------------- wv = W^T @ a ----------------------------------------------
__global__ void k_wvec(const float* __restrict__ W1, const float* __restrict__ a1s,
                       const float* __restrict__ a1d,
                       const float* __restrict__ W2, const float* __restrict__ a2s,
                       const float* __restrict__ a2d) {
    int j = threadIdx.x;
    float s1 = 0.f, d1 = 0.f, s2 = 0.f, d2 = 0.f;
    for (int k = 0; k < D; k++) {
        float w1 = W1[k * D + j], w2 = W2[k * D + j];
        s1 = fmaf(w1, a1s[k], s1); d1 = fmaf(w1, a1d[k], d1);
        s2 = fmaf(w2, a2s[k], s2); d2 = fmaf(w2, a2d[k], d2);
    }
    g_w1s[j] = s1; g_w1d[j] = d1; g_w2s[j] = s2; g_w2d[j] = d2;
}

// ---------------- dual register-tiled SGEMM (f32x2, 8x8 tile) ----------------
// out[r,c] = act(bias[c] + in[r] . W[c,:]); A input fp32 or fp16; output fp32
// or fp16; optional fused attention logits (for fp16-out pass).
__global__ __launch_bounds__(256, 2) void k_gemm2(
    const void* __restrict__ inA, const float* __restrict__ WA,
    const float* __restrict__ biasA, void* __restrict__ outA,
    const void* __restrict__ inB, const float* __restrict__ WB,
    const float* __restrict__ biasB, void* __restrict__ outB,
    int split, int rowsA, int rowsB, int relu, int do_att,
    int in_half, int out_half)
{
    __shared__ float As[BK][BM];
    __shared__ float Bs[BK][128];

    const void *in; const float *W, *bias; void* out; int row0, nrows, attBase;
    if ((int)blockIdx.x < split) {
        in = inA; W = WA; bias = biasA; out = outA;
        row0 = blockIdx.x * BM; nrows = rowsA; attBase = 0;
    } else {
        in = inB; W = WB; bias = biasB; out = outB;
        row0 = (blockIdx.x - split) * BM; nrows = rowsB; attBase = NS;
    }

    const int tid = threadIdx.x;
    const int tr  = (tid >> 4) << 3;
    const int tc  = (tid & 15) << 3;

    unsigned long long acc[8][4];
    #pragma unroll
    for (int i = 0; i < 8; i++)
        #pragma unroll
        for (int j = 0; j < 4; j++) acc[i][j] = 0ull;

    for (int k0 = 0; k0 < D; k0 += BK) {
        __syncthreads();
        #pragma unroll
        for (int i = 0; i < 2; i++) {
            int lin = i * 256 + tid;
            int r   = lin >> 2;
            int jj  = (lin & 3) << 2;
            int gr  = row0 + r;
            float4 v = make_float4(0.f, 0.f, 0.f, 0.f);
            if (gr < nrows) {
                if (in_half) {
                    const __half* inh = (const __half*)in;
                    uint2 u = *(const uint2*)(inh + (size_t)gr * D + k0 + jj);
                    float2 f0 = __half22float2(*reinterpret_cast<const __half2*>(&u.x));
                    float2 f1 = __half22float2(*reinterpret_cast<const __half2*>(&u.y));
                    v = make_float4(f0.x, f0.y, f1.x, f1.y);
                } else {
                    v = *(const float4*)((const float*)in + (size_t)gr * D + k0 + jj);
                }
            }
            As[jj + 0][r] = v.x; As[jj + 1][r] = v.y;
            As[jj + 2][r] = v.z; As[jj + 3][r] = v.w;
            float4 w = *(const float4*)(W + (size_t)r * D + k0 + jj);
            Bs[jj + 0][r] = w.x; Bs[jj + 1][r] = w.y;
            Bs[jj + 2][r] = w.z; Bs[jj + 3][r] = w.w;
        }
        __syncthreads();

        #pragma unroll
        for (int kk = 0; kk < BK; kk++) {
            float4 a0 = *(const float4*)&As[kk][tr];
            float4 a1 = *(const float4*)&As[kk][tr + 4];
            ulonglong2 w0 = *(const ulonglong2*)&Bs[kk][tc];
            ulonglong2 w1 = *(const ulonglong2*)&Bs[kk][tc + 4];
            float a[8] = {a0.x, a0.y, a0.z, a0.w, a1.x, a1.y, a1.z, a1.w};
            #pragma unroll
            for (int i = 0; i < 8; i++) {
                unsigned long long ap = dup2(a[i]);
                ffma2(acc[i][0], ap, w0.x);
                ffma2(acc[i][1], ap, w0.y);
                ffma2(acc[i][2], ap, w1.x);
                ffma2(acc[i][3], ap, w1.y);
            }
        }
    }

    float bcol[8];
    #pragma unroll
    for (int j = 0; j < 8; j++) bcol[j] = bias ? bias[tc + j] : 0.f;

    #pragma unroll
    for (int i = 0; i < 8; i++) {
        int gr = row0 + tr + i;
        float o[8];
        #pragma unroll
        for (int j = 0; j < 4; j++) {
            o[2 * j + 0] = __uint_as_float((unsigned)acc[i][j]) + bcol[2 * j + 0];
            o[2 * j + 1] = __uint_as_float((unsigned)(acc[i][j] >> 32)) + bcol[2 * j + 1];
        }
        if (relu) {
            #pragma unroll
            for (int j = 0; j < 8; j++) o[j] = fmaxf(o[j], 0.f);
        }
        if (gr < nrows) {
            if (out_half) {
                __half h[8];
                #pragma unroll
                for (int j = 0; j < 8; j++) h[j] = __float2half_rn(o[j]);
                *(uint4*)((__half*)out + (size_t)gr * D + tc) = *(uint4*)h;
            } else {
                *(float4*)((float*)out + (size_t)gr * D + tc)     = make_float4(o[0], o[1], o[2], o[3]);
                *(float4*)((float*)out + (size_t)gr * D + tc + 4) = make_float4(o[4], o[5], o[6], o[7]);
            }
        }
        if (do_att) {
            float p1 = 0.f, p2 = 0.f, p3 = 0.f, p4 = 0.f;
            #pragma unroll
            for (int j = 0; j < 8; j++) {
                float ov = o[j];
                p1 = fmaf(ov, g_w1s[tc + j], p1);
                p2 = fmaf(ov, g_w1d[tc + j], p2);
                p3 = fmaf(ov, g_w2s[tc + j], p3);
                p4 = fmaf(ov, g_w2d[tc + j], p4);
            }
            #pragma unroll
            for (int m = 1; m < 16; m <<= 1) {
                p1 += __shfl_xor_sync(0xffffffffu, p1, m);
                p2 += __shfl_xor_sync(0xffffffffu, p2, m);
                p3 += __shfl_xor_sync(0xffffffffu, p3, m);
                p4 += __shfl_xor_sync(0xffffffffu, p4, m);
            }
            if ((tid & 15) == 0 && gr < nrows) {
                int node = attBase + gr;
                g_as1[node] = p1; g_ad1[node] = p2;
                g_as2[node] = p3; g_ad2[node] = p4;
            }
        }
    }
}

// ---------------- fused CSR count over all three edge lists ------------------
__global__ void k_count_all(const void* __restrict__ e0, const void* __restrict__ e1,
                            const void* __restrict__ e2, int E0, int E1, int E2) {
    int t = blockIdx.x * blockDim.x + threadIdx.x;
    if (t < E0) {
        int s = eidx(e0, 0, t);             // paper (conv2 dst)
        int d = eidx(e0, E0, t) + NS;       // author (conv1 dst)
        atomicAdd(&g_cnt[d], 1);
        atomicAdd(&g_cnt[s], 1);
    } else if (t < E0 + E1) {
        int e = t - E0;
        int d = eidx(e1, E1, e);
        if ((unsigned)d < (unsigned)NS) atomicAdd(&g_cnt[d], 1);
    } else if (t < E0 + E1 + E2) {
        int e = t - E0 - E1;
        int d = eidx(e2, E2, e);
        if (d >= NS && d < NN) atomicAdd(&g_cnt[d], 1);
    }
}

// ---------------- CSR scan: single-block exclusive scan over NN --------------
__global__ __launch_bounds__(1024) void k_scan() {
    __shared__ int wsum[32];
    int t = threadIdx.x, lane = t & 31, wid = t >> 5;
    int running = 0;
    for (int base = 0; base < NN; base += 1024) {
        int i = base + t;
        int v = (i < NN) ? g_cnt[i] : 0;
        int incl = v;
        #pragma unroll
        for (int o = 1; o < 32; o <<= 1) {
            int u = __shfl_up_sync(0xffffffffu, incl, o);
            if (lane >= o) incl += u;
        }
        if (lane == 31) wsum[wid] = incl;
        __syncthreads();
        if (wid == 0) {
            int s = wsum[lane];
            #pragma unroll
            for (int o = 1; o < 32; o <<= 1) {
                int u = __shfl_up_sync(0xffffffffu, s, o);
                if (lane >= o) s += u;
            }
            wsum[lane] = s;
        }
        __syncthreads();
        int woff = wid ? wsum[wid - 1] : 0;
        int excl = running + woff + incl - v;
        if (i < NN) { g_ptr[i] = excl; g_pos[i] = excl; }
        running += wsum[31];
        __syncthreads();
    }
    if (t == 0) g_ptr[NN] = running;
}

// ---------------- fused CSR scatter ------------------------------------------
__global__ void k_scat_all(const void* __restrict__ e0, const void* __restrict__ e1,
                           const void* __restrict__ e2, int E0, int E1, int E2) {
    int t = blockIdx.x * blockDim.x + threadIdx.x;
    if (t < E0) {
        int s = eidx(e0, 0, t);
        int d = eidx(e0, E0, t) + NS;
        float w1 = __expf(lrelu(g_as1[s] + g_ad1[d]));
        int p1 = atomicAdd(&g_pos[d], 1);
        g_edge[p1] = make_int2(s, __float_as_int(w1));
        float w2 = __expf(lrelu(g_as2[d] + g_ad2[s]));
        int p2 = atomicAdd(&g_pos[s], 1);
        g_edge[p2] = make_int2(d, __float_as_int(w2));
    } else if (t < E0 + E1) {
        int e = t - E0;
        int d = eidx(e1, E1, e);
        if ((unsigned)d >= (unsigned)NS) return;
        int s = eidx(e1, 0, e);
        float w = __expf(lrelu(g_as2[s] + g_ad2[d]));
        int p = atomicAdd(&g_pos[d], 1);
        g_edge[p] = make_int2(s, __float_as_int(w));
    } else if (t < E0 + E1 + E2) {
        int e = t - E0 - E1;
        int d = eidx(e2, E2, e);
        if (d < NS || d >= NN) return;
        int s = eidx(e2, 0, e);
        float w = __expf(lrelu(g_as1[s] + g_ad1[d]));
        int p = atomicAdd(&g_pos[d], 1);
        g_edge[p] = make_int2(s, __float_as_int(w));
    }
}

// ---------------- aggregation: warp per dst, fp16 gather, fp32 accum ---------
__global__ void k_agg() {
    int i = (blockIdx.x * blockDim.x + threadIdx.x) >> 5;
    int lane = threadIdx.x & 31;
    if (i >= NN) return;
    float w = (i < NS) ? __expf(lrelu(g_as2[i] + g_ad2[i]))
                       : __expf(lrelu(g_as1[i] + g_ad1[i]));
    float denom = w;
    const uint2* xh = (const uint2*)g_xh;     // 4 halfs per lane
    uint2 u = xh[(size_t)i * 32 + lane];
    float2 f0 = __half22float2(*reinterpret_cast<const __half2*>(&u.x));
    float2 f1 = __half22float2(*reinterpret_cast<const __half2*>(&u.y));
    float4 acc = make_float4(f0.x * w, f0.y * w, f1.x * w, f1.y * w);
    int e0 = g_ptr[i], e1 = g_ptr[i + 1];
    for (int e = e0; e < e1; e++) {
        int2 ed = g_edge[e];
        float we = __int_as_float(ed.y);
        uint2 ue = xh[(size_t)ed.x * 32 + lane];
        float2 g0 = __half22float2(*reinterpret_cast<const __half2*>(&ue.x));
        float2 g1 = __half22float2(*reinterpret_cast<const __half2*>(&ue.y));
        acc.x = fmaf(g0.x, we, acc.x);
        acc.y = fmaf(g0.y, we, acc.y);
        acc.z = fmaf(g1.x, we, acc.z);
        acc.w = fmaf(g1.y, we, acc.w);
        denom += we;
    }
    float sc = 1.0f / (denom + 1e-16f);
    __half2 h0 = __floats2half2_rn(acc.x * sc, acc.y * sc);
    __half2 h1 = __floats2half2_rn(acc.z * sc, acc.w * sc);
    uint2 o;
    o.x = *reinterpret_cast<unsigned*>(&h0);
    o.y = *reinterpret_cast<unsigned*>(&h1);
    ((uint2*)g_aggh)[(size_t)i * 32 + lane] = o;
}

// ---------------- driver ------------------------------------------------------
extern "C" void kernel_launch(void* const* d_in, const int* in_sizes, int n_in,
                              void* d_out, int out_size) {
    const void*  edge   = d_in[0];
    const void*  paper  = d_in[1];
    const void*  author = d_in[2];
    const float* x_s = (const float*)d_in[3];
    const float* x_t = (const float*)d_in[4];
    const float* Ws  = (const float*)d_in[5];
    const float* bs  = (const float*)d_in[6];
    const float* Wt  = (const float*)d_in[7];
    const float* bt  = (const float*)d_in[8];
    const float* W1  = (const float*)d_in[9];
    const float* a1s = (const float*)d_in[10];
    const float* a1d = (const float*)d_in[11];
    const float* W2  = (const float*)d_in[12];
    const float* a2s = (const float*)d_in[13];
    const float* a2d = (const float*)d_in[14];
    float* out = (float*)d_out;

    const int E0 = in_sizes[0] / 2;
    const int E1 = in_sizes[1] / 2;
    const int E2 = in_sizes[2] / 2;

    __half* gxh;  cudaGetSymbolAddress((void**)&gxh,  g_xh);
    __half* gah;  cudaGetSymbolAddress((void**)&gah,  g_aggh);
    int* gcnt;    cudaGetSymbolAddress((void**)&gcnt, g_cnt);

    const int GB = (NS + BM - 1) / BM;      // 391 blocks per 50K-row problem
    const int TB = 256;
    const int ET = E0 + E1 + E2;
    const int EBA = (ET + TB - 1) / TB;
    const int WNB = (NN * 32 + TB - 1) / TB;

    k_detect<<<1, 32>>>((const int*)edge);
    k_wvec<<<1, 128>>>(W1, a1s, a1d, W2, a2s, a2d);

    // fused input transforms (fp16 out) + attention logits
    k_gemm2<<<2 * GB, 256>>>(x_s, Ws, bs, gxh,
                             x_t, Wt, bt, gxh + (size_t)NS * D,
                             GB, NS, NT, 0, 1, 0, 1);

    // ---- combined CSR over all NN dst nodes ----
    cudaMemsetAsync(gcnt, 0, NN * sizeof(int));
    k_count_all<<<EBA, TB>>>(edge, paper, author, E0, E1, E2);
    k_scan<<<1, 1024>>>();
    k_scat_all<<<EBA, TB>>>(edge, paper, author, E0, E1, E2);
    k_agg<<<WNB, TB>>>();

    // fused output GEMMs (fp16 in, fp32 out + relu)
    k_gemm2<<<2 * GB, 256>>>(gah + (size_t)NS * D, W1, nullptr, out + (size_t)NS * D,
                             gah, W2, nullptr, out,
                             GB, NS, NS, 1, 0, 1, 0);
}

// round 17
// speedup vs baseline: 1.3146x; 1.0011x over previous
#include <cuda_runtime.h>
#include <cuda_fp16.h>

#define NS   50000
#define NT   50000
#define NN   100000
#define D    128
#define NEG  0.2f

#define BM   128
#define BK   16
#define EMAX 2100000

// ---------------- scratch (device globals) ----------------------------------
__device__ __half g_xh[(size_t)NN * D];     // fp16 transformed features (25.6MB)
__device__ __half g_aggh[(size_t)NN * D];   // fp16 aggregated features
__device__ float  g_as1[NN], g_ad1[NN], g_as2[NN], g_ad2[NN];
__device__ float  g_w1s[D], g_w1d[D], g_w2s[D], g_w2d[D];
__device__ int    g_cnt[NN];
__device__ int    g_ptr[NN + 1];
__device__ int    g_pos[NN];
__device__ int2   g_edge[EMAX];
__device__ int    g_is64;

__device__ __forceinline__ float lrelu(float v) { return v >= 0.f ? v : NEG * v; }

__device__ __forceinline__ void ffma2(unsigned long long& acc,
                                      unsigned long long a, unsigned long long b) {
    asm("fma.rn.f32x2 %0, %1, %2, %0;" : "+l"(acc) : "l"(a), "l"(b));
}
__device__ __forceinline__ unsigned long long dup2(float a) {
    unsigned long long r;
    asm("mov.b64 %0, {%1, %1};" : "=l"(r) : "r"(__float_as_uint(a)));
    return r;
}

// ---------------- index width detection -------------------------------------
__global__ void k_detect(const int* __restrict__ p) {
    if (threadIdx.x == 0) {
        int all0 = 1;
        #pragma unroll
        for (int i = 1; i < 128; i += 2) all0 &= (p[i] == 0);
        g_is64 = all0;
    }
}

__device__ __forceinline__ int eidx(const void* idx, int off, int e) {
    return g_is64 ? (int)((const long long*)idx)[off + e]
                  : ((const int*)idx)[off + e];
}

// ---------------- wv = W^T @ a ----------------------------------------------
__global__ void k_wvec(const float* __restrict__ W1, const float* __restrict__ a1s,
                       const float* __restrict__ a1d,
                       const float* __restrict__ W2, const float* __restrict__ a2s,
                       const float* __restrict__ a2d) {
    int j = threadIdx.x;
    float s1 = 0.f, d1 = 0.f, s2 = 0.f, d2 = 0.f;
    for (int k = 0; k < D; k++) {
        float w1 = W1[k * D + j], w2 = W2[k * D + j];
        s1 = fmaf(w1, a1s[k], s1); d1 = fmaf(w1, a1d[k], d1);
        s2 = fmaf(w2, a2s[k], s2); d2 = fmaf(w2, a2d[k], d2);
    }
    g_w1s[j] = s1; g_w1d[j] = d1; g_w2s[j] = s2; g_w2d[j] = d2;
}

// ---------------- dual register-tiled SGEMM (f32x2, 8x8 tile) ----------------
// out[r,c] = act(bias[c] + in[r] . W[c,:]); A input fp32 or fp16; output fp32
// or fp16; optional fused attention logits (for fp16-out pass).
__global__ __launch_bounds__(256, 2) void k_gemm2(
    const void* __restrict__ inA, const float* __restrict__ WA,
    const float* __restrict__ biasA, void* __restrict__ outA,
    const void* __restrict__ inB, const float* __restrict__ WB,
    const float* __restrict__ biasB, void* __restrict__ outB,
    int split, int rowsA, int rowsB, int relu, int do_att,
    int in_half, int out_half)
{
    __shared__ float As[BK][BM];
    __shared__ float Bs[BK][128];

    const void *in; const float *W, *bias; void* out; int row0, nrows, attBase;
    if ((int)blockIdx.x < split) {
        in = inA; W = WA; bias = biasA; out = outA;
        row0 = blockIdx.x * BM; nrows = rowsA; attBase = 0;
    } else {
        in = inB; W = WB; bias = biasB; out = outB;
        row0 = (blockIdx.x - split) * BM; nrows = rowsB; attBase = NS;
    }

    const int tid = threadIdx.x;
    const int tr  = (tid >> 4) << 3;
    const int tc  = (tid & 15) << 3;

    unsigned long long acc[8][4];
    #pragma unroll
    for (int i = 0; i < 8; i++)
        #pragma unroll
        for (int j = 0; j < 4; j++) acc[i][j] = 0ull;

    for (int k0 = 0; k0 < D; k0 += BK) {
        __syncthreads();
        #pragma unroll
        for (int i = 0; i < 2; i++) {
            int lin = i * 256 + tid;
            int r   = lin >> 2;
            int jj  = (lin & 3) << 2;
            int gr  = row0 + r;
            float4 v = make_float4(0.f, 0.f, 0.f, 0.f);
            if (gr < nrows) {
                if (in_half) {
                    const __half* inh = (const __half*)in;
                    uint2 u = *(const uint2*)(inh + (size_t)gr * D + k0 + jj);
                    float2 f0 = __half22float2(*reinterpret_cast<const __half2*>(&u.x));
                    float2 f1 = __half22float2(*reinterpret_cast<const __half2*>(&u.y));
                    v = make_float4(f0.x, f0.y, f1.x, f1.y);
                } else {
                    v = *(const float4*)((const float*)in + (size_t)gr * D + k0 + jj);
                }
            }
            As[jj + 0][r] = v.x; As[jj + 1][r] = v.y;
            As[jj + 2][r] = v.z; As[jj + 3][r] = v.w;
            float4 w = *(const float4*)(W + (size_t)r * D + k0 + jj);
            Bs[jj + 0][r] = w.x; Bs[jj + 1][r] = w.y;
            Bs[jj + 2][r] = w.z; Bs[jj + 3][r] = w.w;
        }
        __syncthreads();

        #pragma unroll
        for (int kk = 0; kk < BK; kk++) {
            float4 a0 = *(const float4*)&As[kk][tr];
            float4 a1 = *(const float4*)&As[kk][tr + 4];
            ulonglong2 w0 = *(const ulonglong2*)&Bs[kk][tc];
            ulonglong2 w1 = *(const ulonglong2*)&Bs[kk][tc + 4];
            float a[8] = {a0.x, a0.y, a0.z, a0.w, a1.x, a1.y, a1.z, a1.w};
            #pragma unroll
            for (int i = 0; i < 8; i++) {
                unsigned long long ap = dup2(a[i]);
                ffma2(acc[i][0], ap, w0.x);
                ffma2(acc[i][1], ap, w0.y);
                ffma2(acc[i][2], ap, w1.x);
                ffma2(acc[i][3], ap, w1.y);
            }
        }
    }

    float bcol[8];
    #pragma unroll
    for (int j = 0; j < 8; j++) bcol[j] = bias ? bias[tc + j] : 0.f;

    #pragma unroll
    for (int i = 0; i < 8; i++) {
        int gr = row0 + tr + i;
        float o[8];
        #pragma unroll
        for (int j = 0; j < 4; j++) {
            o[2 * j + 0] = __uint_as_float((unsigned)acc[i][j]) + bcol[2 * j + 0];
            o[2 * j + 1] = __uint_as_float((unsigned)(acc[i][j] >> 32)) + bcol[2 * j + 1];
        }
        if (relu) {
            #pragma unroll
            for (int j = 0; j < 8; j++) o[j] = fmaxf(o[j], 0.f);
        }
        if (gr < nrows) {
            if (out_half) {
                __half h[8];
                #pragma unroll
                for (int j = 0; j < 8; j++) h[j] = __float2half_rn(o[j]);
                *(uint4*)((__half*)out + (size_t)gr * D + tc) = *(uint4*)h;
            } else {
                *(float4*)((float*)out + (size_t)gr * D + tc)     = make_float4(o[0], o[1], o[2], o[3]);
                *(float4*)((float*)out + (size_t)gr * D + tc + 4) = make_float4(o[4], o[5], o[6], o[7]);
            }
        }
        if (do_att) {
            float p1 = 0.f, p2 = 0.f, p3 = 0.f, p4 = 0.f;
            #pragma unroll
            for (int j = 0; j < 8; j++) {
                float ov = o[j];
                p1 = fmaf(ov, g_w1s[tc + j], p1);
                p2 = fmaf(ov, g_w1d[tc + j], p2);
                p3 = fmaf(ov, g_w2s[tc + j], p3);
                p4 = fmaf(ov, g_w2d[tc + j], p4);
            }
            #pragma unroll
            for (int m = 1; m < 16; m <<= 1) {
                p1 += __shfl_xor_sync(0xffffffffu, p1, m);
                p2 += __shfl_xor_sync(0xffffffffu, p2, m);
                p3 += __shfl_xor_sync(0xffffffffu, p3, m);
                p4 += __shfl_xor_sync(0xffffffffu, p4, m);
            }
            if ((tid & 15) == 0 && gr < nrows) {
                int node = attBase + gr;
                g_as1[node] = p1; g_ad1[node] = p2;
                g_as2[node] = p3; g_ad2[node] = p4;
            }
        }
    }
}

// ---------------- fused CSR count over all three edge lists ------------------
__global__ void k_count_all(const void* __restrict__ e0, const void* __restrict__ e1,
                            const void* __restrict__ e2, int E0, int E1, int E2) {
    int t = blockIdx.x * blockDim.x + threadIdx.x;
    if (t < E0) {
        int s = eidx(e0, 0, t);             // paper (conv2 dst)
        int d = eidx(e0, E0, t) + NS;       // author (conv1 dst)
        atomicAdd(&g_cnt[d], 1);
        atomicAdd(&g_cnt[s], 1);
    } else if (t < E0 + E1) {
        int e = t - E0;
        int d = eidx(e1, E1, e);
        if ((unsigned)d < (unsigned)NS) atomicAdd(&g_cnt[d], 1);
    } else if (t < E0 + E1 + E2) {
        int e = t - E0 - E1;
        int d = eidx(e2, E2, e);
        if (d >= NS && d < NN) atomicAdd(&g_cnt[d], 1);
    }
}

// ---------------- CSR scan: single-block exclusive scan over NN --------------
__global__ __launch_bounds__(1024) void k_scan() {
    __shared__ int wsum[32];
    int t = threadIdx.x, lane = t & 31, wid = t >> 5;
    int running = 0;
    for (int base = 0; base < NN; base += 1024) {
        int i = base + t;
        int v = (i < NN) ? g_cnt[i] : 0;
        int incl = v;
        #pragma unroll
        for (int o = 1; o < 32; o <<= 1) {
            int u = __shfl_up_sync(0xffffffffu, incl, o);
            if (lane >= o) incl += u;
        }
        if (lane == 31) wsum[wid] = incl;
        __syncthreads();
        if (wid == 0) {
            int s = wsum[lane];
            #pragma unroll
            for (int o = 1; o < 32; o <<= 1) {
                int u = __shfl_up_sync(0xffffffffu, s, o);
                if (lane >= o) s += u;
            }
            wsum[lane] = s;
        }
        __syncthreads();
        int woff = wid ? wsum[wid - 1] : 0;
        int excl = running + woff + incl - v;
        if (i < NN) { g_ptr[i] = excl; g_pos[i] = excl; }
        running += wsum[31];
        __syncthreads();
    }
    if (t == 0) g_ptr[NN] = running;
}

// ---------------- fused CSR scatter ------------------------------------------
__global__ void k_scat_all(const void* __restrict__ e0, const void* __restrict__ e1,
                           const void* __restrict__ e2, int E0, int E1, int E2) {
    int t = blockIdx.x * blockDim.x + threadIdx.x;
    if (t < E0) {
        int s = eidx(e0, 0, t);
        int d = eidx(e0, E0, t) + NS;
        float w1 = __expf(lrelu(g_as1[s] + g_ad1[d]));
        int p1 = atomicAdd(&g_pos[d], 1);
        g_edge[p1] = make_int2(s, __float_as_int(w1));
        float w2 = __expf(lrelu(g_as2[d] + g_ad2[s]));
        int p2 = atomicAdd(&g_pos[s], 1);
        g_edge[p2] = make_int2(d, __float_as_int(w2));
    } else if (t < E0 + E1) {
        int e = t - E0;
        int d = eidx(e1, E1, e);
        if ((unsigned)d >= (unsigned)NS) return;
        int s = eidx(e1, 0, e);
        float w = __expf(lrelu(g_as2[s] + g_ad2[d]));
        int p = atomicAdd(&g_pos[d], 1);
        g_edge[p] = make_int2(s, __float_as_int(w));
    } else if (t < E0 + E1 + E2) {
        int e = t - E0 - E1;
        int d = eidx(e2, E2, e);
        if (d < NS || d >= NN) return;
        int s = eidx(e2, 0, e);
        float w = __expf(lrelu(g_as1[s] + g_ad1[d]));
        int p = atomicAdd(&g_pos[d], 1);
        g_edge[p] = make_int2(s, __float_as_int(w));
    }
}

// ---------------- aggregation: warp per dst, fp16 gather, fp32 accum ---------
__global__ void k_agg() {
    int i = (blockIdx.x * blockDim.x + threadIdx.x) >> 5;
    int lane = threadIdx.x & 31;
    if (i >= NN) return;
    float w = (i < NS) ? __expf(lrelu(g_as2[i] + g_ad2[i]))
                       : __expf(lrelu(g_as1[i] + g_ad1[i]));
    float denom = w;
    const uint2* xh = (const uint2*)g_xh;     // 4 halfs per lane
    uint2 u = xh[(size_t)i * 32 + lane];
    float2 f0 = __half22float2(*reinterpret_cast<const __half2*>(&u.x));
    float2 f1 = __half22float2(*reinterpret_cast<const __half2*>(&u.y));
    float4 acc = make_float4(f0.x * w, f0.y * w, f1.x * w, f1.y * w);
    int e0 = g_ptr[i], e1 = g_ptr[i + 1];
    for (int e = e0; e < e1; e++) {
        int2 ed = g_edge[e];
        float we = __int_as_float(ed.y);
        uint2 ue = xh[(size_t)ed.x * 32 + lane];
        float2 g0 = __half22float2(*reinterpret_cast<const __half2*>(&ue.x));
        float2 g1 = __half22float2(*reinterpret_cast<const __half2*>(&ue.y));
        acc.x = fmaf(g0.x, we, acc.x);
        acc.y = fmaf(g0.y, we, acc.y);
        acc.z = fmaf(g1.x, we, acc.z);
        acc.w = fmaf(g1.y, we, acc.w);
        denom += we;
    }
    float sc = 1.0f / (denom + 1e-16f);
    __half2 h0 = __floats2half2_rn(acc.x * sc, acc.y * sc);
    __half2 h1 = __floats2half2_rn(acc.z * sc, acc.w * sc);
    uint2 o;
    o.x = *reinterpret_cast<unsigned*>(&h0);
    o.y = *reinterpret_cast<unsigned*>(&h1);
    ((uint2*)g_aggh)[(size_t)i * 32 + lane] = o;
}

// ---------------- driver ------------------------------------------------------
extern "C" void kernel_launch(void* const* d_in, const int* in_sizes, int n_in,
                              void* d_out, int out_size) {
    const void*  edge   = d_in[0];
    const void*  paper  = d_in[1];
    const void*  author = d_in[2];
    const float* x_s = (const float*)d_in[3];
    const float* x_t = (const float*)d_in[4];
    const float* Ws  = (const float*)d_in[5];
    const float* bs  = (const float*)d_in[6];
    const float* Wt  = (const float*)d_in[7];
    const float* bt  = (const float*)d_in[8];
    const float* W1  = (const float*)d_in[9];
    const float* a1s = (const float*)d_in[10];
    const float* a1d = (const float*)d_in[11];
    const float* W2  = (const float*)d_in[12];
    const float* a2s = (const float*)d_in[13];
    const float* a2d = (const float*)d_in[14];
    float* out = (float*)d_out;

    const int E0 = in_sizes[0] / 2;
    const int E1 = in_sizes[1] / 2;
    const int E2 = in_sizes[2] / 2;

    __half* gxh;  cudaGetSymbolAddress((void**)&gxh,  g_xh);
    __half* gah;  cudaGetSymbolAddress((void**)&gah,  g_aggh);
    int* gcnt;    cudaGetSymbolAddress((void**)&gcnt, g_cnt);

    const int GB = (NS + BM - 1) / BM;      // 391 blocks per 50K-row problem
    const int TB = 256;
    const int ET = E0 + E1 + E2;
    const int EBA = (ET + TB - 1) / TB;
    const int WNB = (NN * 32 + TB - 1) / TB;

    k_detect<<<1, 32>>>((const int*)edge);
    k_wvec<<<1, 128>>>(W1, a1s, a1d, W2, a2s, a2d);

    // fused input transforms (fp16 out) + attention logits
    k_gemm2<<<2 * GB, 256>>>(x_s, Ws, bs, gxh,
                             x_t, Wt, bt, gxh + (size_t)NS * D,
                             GB, NS, NT, 0, 1, 0, 1);

    // ---- combined CSR over all NN dst nodes ----
    cudaMemsetAsync(gcnt, 0, NN * sizeof(int));
    k_count_all<<<EBA, TB>>>(edge, paper, author, E0, E1, E2);
    k_scan<<<1, 1024>>>();
    k_scat_all<<<EBA, TB>>>(edge, paper, author, E0, E1, E2);
    k_agg<<<WNB, TB>>>();

    // fused output GEMMs (fp16 in, fp32 out + relu)
    k_gemm2<<<2 * GB, 256>>>(gah + (size_t)NS * D, W1, nullptr, out + (size_t)NS * D,
                             gah, W2, nullptr, out,
                             GB, NS, NS, 1, 0, 1, 0);
}